// round 2
// baseline (speedup 1.0000x reference)
#include <cuda_runtime.h>
#include <cstdint>

// ---------------------------------------------------------------------------
// GAT encoder: 3 layers.
//   L0: Fin=128 -> H=4,C=32 (HC=128), relu
//   L1: 128 -> (4,32), relu
//   L2: 128 -> (1,64)
// Edges: E given + N self loops (ET = E + N), decoded once to int32.
// ---------------------------------------------------------------------------

#define MAXN 50000
#define MAXE 800000
#define MAXET (MAXE + MAXN)

__device__ __align__(16) float g_feat[MAXN * 128];
__device__ __align__(16) float g_in  [MAXN * 128];
__device__ __align__(16) float g_acc [MAXN * 128];
__device__ __align__(16) float g_as  [MAXN * 4];
__device__ __align__(16) float g_ad  [MAXN * 4];
__device__ __align__(16) float g_m   [MAXN * 4];
__device__ __align__(16) float g_den [MAXN * 4];
__device__ __align__(16) float g_ex  [MAXET * 4];
__device__ int g_src[MAXET];
__device__ int g_dst[MAXET];
__device__ int g_is64;

// ---------------------------------------------------------------------------
// Edge-index decode: probe dtype (int64 vs int32) then expand + self loops.
// int64 case: odd 32-bit words are high halves of small positive ints -> 0.
// ---------------------------------------------------------------------------
__global__ void detect_k(const unsigned int* __restrict__ raw) {
    unsigned int o = 0;
#pragma unroll
    for (int j = 1; j < 128; j += 2) o |= raw[j];
    g_is64 = (o == 0u) ? 1 : 0;
}

__global__ void decode_k(const void* __restrict__ raw, int E, int ET,
                         int* __restrict__ src, int* __restrict__ dst) {
    int e = blockIdx.x * blockDim.x + threadIdx.x;
    if (e >= ET) return;
    int s, d;
    if (e < E) {
        if (g_is64) {
            const long long* p = (const long long*)raw;
            s = (int)p[e];
            d = (int)p[E + e];
        } else {
            const int* p = (const int*)raw;
            s = p[e];
            d = p[E + e];
        }
    } else {
        s = d = e - E;
    }
    src[e] = s;
    dst[e] = d;
}

// ---------------------------------------------------------------------------
// GEMM: O[M,NC] = X[M,128] @ W[128,NC].  Block: 256 thr, 128 rows.
// ---------------------------------------------------------------------------
template <int NC>
__global__ __launch_bounds__(256) void gemm_k(const float* __restrict__ X,
                                              const float* __restrict__ W,
                                              float* __restrict__ O, int M) {
    constexpr int K = 128, KCH = 32, ROWS = 128;
    constexpr int CG = NC / 4;   // cols per colgroup
    constexpr int C4 = CG / 4;   // float4 per row per thread
    __shared__ float  Xs[ROWS][KCH + 1];
    __shared__ float4 Ws[KCH][NC / 4];

    int tid = threadIdx.x;
    int cg = tid >> 6;
    int r  = tid & 63;
    int rowbase = blockIdx.x * ROWS;

    float4 aA[C4], aB[C4];
#pragma unroll
    for (int j = 0; j < C4; j++) {
        aA[j] = make_float4(0.f, 0.f, 0.f, 0.f);
        aB[j] = make_float4(0.f, 0.f, 0.f, 0.f);
    }

    for (int kb = 0; kb < K; kb += KCH) {
        for (int i = tid; i < ROWS * (KCH / 4); i += 256) {
            int rr = i >> 3, q = i & 7;
            int gr = rowbase + rr;
            float4 v = make_float4(0.f, 0.f, 0.f, 0.f);
            if (gr < M)
                v = *reinterpret_cast<const float4*>(X + (size_t)gr * K + kb + q * 4);
            Xs[rr][q * 4 + 0] = v.x;
            Xs[rr][q * 4 + 1] = v.y;
            Xs[rr][q * 4 + 2] = v.z;
            Xs[rr][q * 4 + 3] = v.w;
        }
        for (int i = tid; i < KCH * (NC / 4); i += 256) {
            int kk = i / (NC / 4), q = i % (NC / 4);
            Ws[kk][q] = *reinterpret_cast<const float4*>(W + (size_t)(kb + kk) * NC + q * 4);
        }
        __syncthreads();
#pragma unroll 4
        for (int kk = 0; kk < KCH; kk++) {
            float xa = Xs[r][kk];
            float xb = Xs[r + 64][kk];
#pragma unroll
            for (int j = 0; j < C4; j++) {
                float4 w = Ws[kk][cg * C4 + j];
                aA[j].x += xa * w.x; aA[j].y += xa * w.y;
                aA[j].z += xa * w.z; aA[j].w += xa * w.w;
                aB[j].x += xb * w.x; aB[j].y += xb * w.y;
                aB[j].z += xb * w.z; aB[j].w += xb * w.w;
            }
        }
        __syncthreads();
    }

    int rowA = rowbase + r, rowB = rowbase + r + 64;
    if (rowA < M) {
#pragma unroll
        for (int j = 0; j < C4; j++)
            *reinterpret_cast<float4*>(O + (size_t)rowA * NC + cg * CG + j * 4) = aA[j];
    }
    if (rowB < M) {
#pragma unroll
        for (int j = 0; j < C4; j++)
            *reinterpret_cast<float4*>(O + (size_t)rowB * NC + cg * CG + j * 4) = aB[j];
    }
}

// ---------------------------------------------------------------------------
template <int HH, int C>
__global__ void alpha_k(const float* __restrict__ feat,
                        const float* __restrict__ avs,
                        const float* __restrict__ avd,
                        float* __restrict__ os, float* __restrict__ od, int N) {
    int i = blockIdx.x * blockDim.x + threadIdx.x;
    if (i >= N * HH) return;
    int n = i / HH, h = i % HH;
    const float* f = feat + (size_t)n * HH * C + h * C;
    float s = 0.f, d = 0.f;
#pragma unroll
    for (int c = 0; c < C; c++) {
        float fv = f[c];
        s += fv * __ldg(avs + h * C + c);
        d += fv * __ldg(avd + h * C + c);
    }
    os[i] = s;
    od[i] = d;
}

__global__ void init_k(float* __restrict__ acc, float* __restrict__ m,
                       float* __restrict__ den, int nhc, int nh) {
    int i = blockIdx.x * blockDim.x + threadIdx.x;
    if (i < nhc) acc[i] = 0.f;
    if (i < nh) {
        m[i] = __int_as_float(0xff800000);  // -inf
        den[i] = 0.f;
    }
}

__device__ __forceinline__ void atomicMaxF(float* a, float v) {
    if (v >= 0.f)
        atomicMax(reinterpret_cast<int*>(a), __float_as_int(v));
    else
        atomicMin(reinterpret_cast<unsigned int*>(a), __float_as_uint(v));
}

template <int HH>
__global__ void pass1_k(const int* __restrict__ src, const int* __restrict__ dst,
                        int ET,
                        const float* __restrict__ as_, const float* __restrict__ ad_,
                        float* __restrict__ m) {
    int i = blockIdx.x * blockDim.x + threadIdx.x;
    if (i >= ET * HH) return;
    int e = i / HH, h = i % HH;
    int s = src[e], d = dst[e];
    float v = as_[s * HH + h] + ad_[d * HH + h];
    v = v > 0.f ? v : 0.2f * v;
    atomicMaxF(&m[d * HH + h], v);
}

template <int HH>
__global__ void pass2_k(const int* __restrict__ src, const int* __restrict__ dst,
                        int ET,
                        const float* __restrict__ as_, const float* __restrict__ ad_,
                        const float* __restrict__ m, float* __restrict__ den,
                        float* __restrict__ exb) {
    int i = blockIdx.x * blockDim.x + threadIdx.x;
    if (i >= ET * HH) return;
    int e = i / HH, h = i % HH;
    int s = src[e], d = dst[e];
    float v = as_[s * HH + h] + ad_[d * HH + h];
    v = v > 0.f ? v : 0.2f * v;
    float ex = expf(v - m[d * HH + h]);
    exb[i] = ex;
    atomicAdd(&den[d * HH + h], ex);
}

// warp per edge; lane = float4 slot of the HC-wide feature row
template <int HH, int C>
__global__ void pass3_k(const int* __restrict__ src, const int* __restrict__ dst,
                        int ET,
                        const float* __restrict__ feat,
                        const float* __restrict__ exb,
                        const float* __restrict__ den,
                        float* __restrict__ acc) {
    constexpr int HC = HH * C, SLOTS = HC / 4, CQ = C / 4;
    int gt = blockIdx.x * blockDim.x + threadIdx.x;
    int e = gt >> 5;
    int lane = gt & 31;
    if (e >= ET) return;
    if (lane >= SLOTS) return;
    int s = src[e], d = dst[e];
    int h = lane / CQ;
    float w = exb[(size_t)e * HH + h] / (den[d * HH + h] + 1e-16f);
    float4 f = reinterpret_cast<const float4*>(feat)[(size_t)s * SLOTS + lane];
    float* p = acc + (size_t)d * HC + lane * 4;
    asm volatile("red.global.add.v4.f32 [%0], {%1,%2,%3,%4};"
                 :: "l"(p), "f"(f.x * w), "f"(f.y * w), "f"(f.z * w), "f"(f.w * w)
                 : "memory");
}

template <int HC, bool RELU>
__global__ void fin_k(const float* __restrict__ acc, const float* __restrict__ b,
                      float* __restrict__ out, int total) {
    int i = blockIdx.x * blockDim.x + threadIdx.x;
    if (i >= total) return;
    float v = acc[i] + __ldg(b + (i & (HC - 1)));
    if (RELU) v = v > 0.f ? v : 0.f;
    out[i] = v;
}

// ---------------------------------------------------------------------------
extern "C" void kernel_launch(void* const* d_in, const int* in_sizes, int n_in,
                              void* d_out, int out_size) {
    const float* x   = (const float*)d_in[0];
    const void*  ei  = d_in[1];
    const float* W0  = (const float*)d_in[2];
    const float* as0 = (const float*)d_in[3];
    const float* ad0 = (const float*)d_in[4];
    const float* b0  = (const float*)d_in[5];
    const float* W1  = (const float*)d_in[6];
    const float* as1 = (const float*)d_in[7];
    const float* ad1 = (const float*)d_in[8];
    const float* b1  = (const float*)d_in[9];
    const float* W2  = (const float*)d_in[10];
    const float* as2 = (const float*)d_in[11];
    const float* ad2 = (const float*)d_in[12];
    const float* b2  = (const float*)d_in[13];
    float* out = (float*)d_out;

    int N = in_sizes[0] / 128;
    int E = in_sizes[1] / 2;
    int ET = E + N;

    float *feat, *inb, *acc, *asb, *adb, *mb, *db, *exb;
    int *srcp, *dstp;
    cudaGetSymbolAddress((void**)&feat, g_feat);
    cudaGetSymbolAddress((void**)&inb,  g_in);
    cudaGetSymbolAddress((void**)&acc,  g_acc);
    cudaGetSymbolAddress((void**)&asb,  g_as);
    cudaGetSymbolAddress((void**)&adb,  g_ad);
    cudaGetSymbolAddress((void**)&mb,   g_m);
    cudaGetSymbolAddress((void**)&db,   g_den);
    cudaGetSymbolAddress((void**)&exb,  g_ex);
    cudaGetSymbolAddress((void**)&srcp, g_src);
    cudaGetSymbolAddress((void**)&dstp, g_dst);

    const int TB = 256;
    int gemmGrid = (N + 127) / 128;

    detect_k<<<1, 1>>>((const unsigned int*)ei);
    decode_k<<<(ET + TB - 1) / TB, TB>>>(ei, E, ET, srcp, dstp);

    // ---------------- Layer 0 ----------------
    gemm_k<128><<<gemmGrid, TB>>>(x, W0, feat, N);
    alpha_k<4, 32><<<(N * 4 + TB - 1) / TB, TB>>>(feat, as0, ad0, asb, adb, N);
    init_k<<<(N * 128 + TB - 1) / TB, TB>>>(acc, mb, db, N * 128, N * 4);
    pass1_k<4><<<(ET * 4 + TB - 1) / TB, TB>>>(srcp, dstp, ET, asb, adb, mb);
    pass2_k<4><<<(ET * 4 + TB - 1) / TB, TB>>>(srcp, dstp, ET, asb, adb, mb, db, exb);
    pass3_k<4, 32><<<((long)ET * 32 + TB - 1) / TB, TB>>>(srcp, dstp, ET, feat, exb, db, acc);
    fin_k<128, true><<<(N * 128 + TB - 1) / TB, TB>>>(acc, b0, inb, N * 128);

    // ---------------- Layer 1 ----------------
    gemm_k<128><<<gemmGrid, TB>>>(inb, W1, feat, N);
    alpha_k<4, 32><<<(N * 4 + TB - 1) / TB, TB>>>(feat, as1, ad1, asb, adb, N);
    init_k<<<(N * 128 + TB - 1) / TB, TB>>>(acc, mb, db, N * 128, N * 4);
    pass1_k<4><<<(ET * 4 + TB - 1) / TB, TB>>>(srcp, dstp, ET, asb, adb, mb);
    pass2_k<4><<<(ET * 4 + TB - 1) / TB, TB>>>(srcp, dstp, ET, asb, adb, mb, db, exb);
    pass3_k<4, 32><<<((long)ET * 32 + TB - 1) / TB, TB>>>(srcp, dstp, ET, feat, exb, db, acc);
    fin_k<128, true><<<(N * 128 + TB - 1) / TB, TB>>>(acc, b1, inb, N * 128);

    // ---------------- Layer 2 ----------------
    gemm_k<64><<<gemmGrid, TB>>>(inb, W2, feat, N);
    alpha_k<1, 64><<<(N + TB - 1) / TB, TB>>>(feat, as2, ad2, asb, adb, N);
    init_k<<<(N * 64 + TB - 1) / TB, TB>>>(acc, mb, db, N * 64, N);
    pass1_k<1><<<(ET + TB - 1) / TB, TB>>>(srcp, dstp, ET, asb, adb, mb);
    pass2_k<1><<<(ET + TB - 1) / TB, TB>>>(srcp, dstp, ET, asb, adb, mb, db, exb);
    pass3_k<1, 64><<<((long)ET * 32 + TB - 1) / TB, TB>>>(srcp, dstp, ET, feat, exb, db, acc);
    fin_k<64, false><<<(N * 64 + TB - 1) / TB, TB>>>(acc, b2, out, N * 64);
}

// round 3
// speedup vs baseline: 1.2887x; 1.2887x over previous
#include <cuda_runtime.h>
#include <cstdint>

// ---------------------------------------------------------------------------
// GAT encoder, 3 layers. Round 3: alpha fused into GEMM epilogue, max-pass
// removed (softmax shift-invariance), vectorized denominator pass.
// ---------------------------------------------------------------------------

#define MAXN 50000
#define MAXE 800000
#define MAXET (MAXE + MAXN)

__device__ __align__(16) float g_feat[MAXN * 128];
__device__ __align__(16) float g_in  [MAXN * 128];
__device__ __align__(16) float g_acc [MAXN * 128];
__device__ __align__(16) float g_as  [MAXN * 4];
__device__ __align__(16) float g_ad  [MAXN * 4];
__device__ __align__(16) float g_den [MAXN * 4];
__device__ __align__(16) float g_ex  [MAXET * 4];
__device__ int g_src[MAXET];
__device__ int g_dst[MAXET];
__device__ int g_is64;

// ---------------------------------------------------------------------------
__global__ void detect_k(const unsigned int* __restrict__ raw) {
    unsigned int o = 0;
#pragma unroll
    for (int j = 1; j < 128; j += 2) o |= raw[j];
    g_is64 = (o == 0u) ? 1 : 0;
}

__global__ void decode_k(const void* __restrict__ raw, int E, int ET,
                         int* __restrict__ src, int* __restrict__ dst) {
    int e = blockIdx.x * blockDim.x + threadIdx.x;
    if (e >= ET) return;
    int s, d;
    if (e < E) {
        if (g_is64) {
            const long long* p = (const long long*)raw;
            s = (int)p[e];
            d = (int)p[E + e];
        } else {
            const int* p = (const int*)raw;
            s = p[e];
            d = p[E + e];
        }
    } else {
        s = d = e - E;
    }
    src[e] = s;
    dst[e] = d;
}

// ---------------------------------------------------------------------------
// GEMM + fused alpha epilogue.
// O[M,NC] = X[M,128] @ W[128,NC]; also os/od[n,h] = h[n,head] . avs/avd[head].
// Block 256 thr handles 128 rows. Thread (cg=tid/64, r=tid%64) computes
// rows {r, r+64} x colgroup cg (NC/4 cols).
//   NC=128 (H=4,C=32): colgroup == head; dot local to thread.
//   NC=64  (H=1,C=64): partial dot, shared-memory reduce over 4 cg threads.
// ---------------------------------------------------------------------------
template <int NC, int HH>
__global__ __launch_bounds__(256) void gemm_k(const float* __restrict__ X,
                                              const float* __restrict__ W,
                                              float* __restrict__ O,
                                              const float* __restrict__ avs,
                                              const float* __restrict__ avd,
                                              float* __restrict__ os,
                                              float* __restrict__ od, int M) {
    constexpr int K = 128, KCH = 32, ROWS = 128;
    constexpr int CG = NC / 4;   // cols per colgroup
    constexpr int C4 = CG / 4;   // float4 per row per thread
    __shared__ float  Xs[ROWS][KCH + 1];
    __shared__ float4 Ws[KCH][NC / 4];

    int tid = threadIdx.x;
    int cg = tid >> 6;
    int r  = tid & 63;
    int rowbase = blockIdx.x * ROWS;

    float4 aA[C4], aB[C4];
#pragma unroll
    for (int j = 0; j < C4; j++) {
        aA[j] = make_float4(0.f, 0.f, 0.f, 0.f);
        aB[j] = make_float4(0.f, 0.f, 0.f, 0.f);
    }

    for (int kb = 0; kb < K; kb += KCH) {
        for (int i = tid; i < ROWS * (KCH / 4); i += 256) {
            int rr = i >> 3, q = i & 7;
            int gr = rowbase + rr;
            float4 v = make_float4(0.f, 0.f, 0.f, 0.f);
            if (gr < M)
                v = *reinterpret_cast<const float4*>(X + (size_t)gr * K + kb + q * 4);
            Xs[rr][q * 4 + 0] = v.x;
            Xs[rr][q * 4 + 1] = v.y;
            Xs[rr][q * 4 + 2] = v.z;
            Xs[rr][q * 4 + 3] = v.w;
        }
        for (int i = tid; i < KCH * (NC / 4); i += 256) {
            int kk = i / (NC / 4), q = i % (NC / 4);
            Ws[kk][q] = *reinterpret_cast<const float4*>(W + (size_t)(kb + kk) * NC + q * 4);
        }
        __syncthreads();
#pragma unroll 4
        for (int kk = 0; kk < KCH; kk++) {
            float xa = Xs[r][kk];
            float xb = Xs[r + 64][kk];
#pragma unroll
            for (int j = 0; j < C4; j++) {
                float4 w = Ws[kk][cg * C4 + j];
                aA[j].x += xa * w.x; aA[j].y += xa * w.y;
                aA[j].z += xa * w.z; aA[j].w += xa * w.w;
                aB[j].x += xb * w.x; aB[j].y += xb * w.y;
                aB[j].z += xb * w.z; aB[j].w += xb * w.w;
            }
        }
        __syncthreads();
    }

    int rowA = rowbase + r, rowB = rowbase + r + 64;
    if (rowA < M) {
#pragma unroll
        for (int j = 0; j < C4; j++)
            *reinterpret_cast<float4*>(O + (size_t)rowA * NC + cg * CG + j * 4) = aA[j];
    }
    if (rowB < M) {
#pragma unroll
        for (int j = 0; j < C4; j++)
            *reinterpret_cast<float4*>(O + (size_t)rowB * NC + cg * CG + j * 4) = aB[j];
    }

    // ---- fused alpha epilogue ----
    float sA = 0.f, dA = 0.f, sB = 0.f, dB = 0.f;
#pragma unroll
    for (int j = 0; j < C4; j++) {
        float4 vs = *reinterpret_cast<const float4*>(avs + cg * CG + j * 4);
        float4 vd = *reinterpret_cast<const float4*>(avd + cg * CG + j * 4);
        sA += aA[j].x * vs.x + aA[j].y * vs.y + aA[j].z * vs.z + aA[j].w * vs.w;
        dA += aA[j].x * vd.x + aA[j].y * vd.y + aA[j].z * vd.z + aA[j].w * vd.w;
        sB += aB[j].x * vs.x + aB[j].y * vs.y + aB[j].z * vs.z + aB[j].w * vs.w;
        dB += aB[j].x * vd.x + aB[j].y * vd.y + aB[j].z * vd.z + aB[j].w * vd.w;
    }

    if (HH == 4) {
        // colgroup == head
        if (rowA < M) { os[rowA * 4 + cg] = sA; od[rowA * 4 + cg] = dA; }
        if (rowB < M) { os[rowB * 4 + cg] = sB; od[rowB * 4 + cg] = dB; }
    } else {
        // single head spanning all 4 colgroups: shared-memory reduce
        __shared__ float4 red[64][4];  // (sA,dA,sB,dB) per (r, cg)
        red[r][cg] = make_float4(sA, dA, sB, dB);
        __syncthreads();
        if (cg == 0) {
            float4 t0 = red[r][0], t1 = red[r][1], t2 = red[r][2], t3 = red[r][3];
            float ssA = t0.x + t1.x + t2.x + t3.x;
            float ddA = t0.y + t1.y + t2.y + t3.y;
            float ssB = t0.z + t1.z + t2.z + t3.z;
            float ddB = t0.w + t1.w + t2.w + t3.w;
            if (rowA < M) { os[rowA] = ssA; od[rowA] = ddA; }
            if (rowB < M) { os[rowB] = ssB; od[rowB] = ddB; }
        }
    }
}

// ---------------------------------------------------------------------------
__global__ void init_k(float* __restrict__ acc, float* __restrict__ den,
                       int nhc, int nh) {
    int i = blockIdx.x * blockDim.x + threadIdx.x;
    if (i < nhc) acc[i] = 0.f;
    if (i < nh) den[i] = 0.f;
}

// pass2: per-edge, all heads vectorized. ex = exp(leakyrelu(as+ad)); den += ex.
__global__ void pass2_v4_k(const int* __restrict__ src, const int* __restrict__ dst,
                           int ET,
                           const float* __restrict__ as_, const float* __restrict__ ad_,
                           float* __restrict__ den, float* __restrict__ exb) {
    int e = blockIdx.x * blockDim.x + threadIdx.x;
    if (e >= ET) return;
    int s = src[e], d = dst[e];
    float4 va = reinterpret_cast<const float4*>(as_)[s];
    float4 vd = reinterpret_cast<const float4*>(ad_)[d];
    float4 ex;
    float v;
    v = va.x + vd.x; v = v > 0.f ? v : 0.2f * v; ex.x = __expf(v);
    v = va.y + vd.y; v = v > 0.f ? v : 0.2f * v; ex.y = __expf(v);
    v = va.z + vd.z; v = v > 0.f ? v : 0.2f * v; ex.z = __expf(v);
    v = va.w + vd.w; v = v > 0.f ? v : 0.2f * v; ex.w = __expf(v);
    reinterpret_cast<float4*>(exb)[e] = ex;
    float* p = den + (size_t)d * 4;
    asm volatile("red.global.add.v4.f32 [%0], {%1,%2,%3,%4};"
                 :: "l"(p), "f"(ex.x), "f"(ex.y), "f"(ex.z), "f"(ex.w) : "memory");
}

__global__ void pass2_s_k(const int* __restrict__ src, const int* __restrict__ dst,
                          int ET,
                          const float* __restrict__ as_, const float* __restrict__ ad_,
                          float* __restrict__ den, float* __restrict__ exb) {
    int e = blockIdx.x * blockDim.x + threadIdx.x;
    if (e >= ET) return;
    int s = src[e], d = dst[e];
    float v = as_[s] + ad_[d];
    v = v > 0.f ? v : 0.2f * v;
    float ex = __expf(v);
    exb[e] = ex;
    atomicAdd(&den[d], ex);
}

// pass3 HC=128: warp per edge, lane = float4 slot.
__global__ void pass3_128_k(const int* __restrict__ src, const int* __restrict__ dst,
                            int ET,
                            const float* __restrict__ feat,
                            const float* __restrict__ exb,
                            const float* __restrict__ den,
                            float* __restrict__ acc) {
    int gt = blockIdx.x * blockDim.x + threadIdx.x;
    int e = gt >> 5;
    int lane = gt & 31;
    if (e >= ET) return;
    int s = src[e], d = dst[e];
    int h = lane >> 3;
    float w = exb[(size_t)e * 4 + h] / (den[(size_t)d * 4 + h] + 1e-16f);
    float4 f = reinterpret_cast<const float4*>(feat)[(size_t)s * 32 + lane];
    float* p = acc + (size_t)d * 128 + lane * 4;
    asm volatile("red.global.add.v4.f32 [%0], {%1,%2,%3,%4};"
                 :: "l"(p), "f"(f.x * w), "f"(f.y * w), "f"(f.z * w), "f"(f.w * w)
                 : "memory");
}

// pass3 HC=64: half-warp per edge (2 edges per warp).
__global__ void pass3_64_k(const int* __restrict__ src, const int* __restrict__ dst,
                           int ET,
                           const float* __restrict__ feat,
                           const float* __restrict__ exb,
                           const float* __restrict__ den,
                           float* __restrict__ acc) {
    int gt = blockIdx.x * blockDim.x + threadIdx.x;
    int e = gt >> 4;
    int lane = gt & 15;
    if (e >= ET) return;
    int s = src[e], d = dst[e];
    float w = exb[e] / (den[d] + 1e-16f);
    float4 f = reinterpret_cast<const float4*>(feat)[(size_t)s * 16 + lane];
    float* p = acc + (size_t)d * 64 + lane * 4;
    asm volatile("red.global.add.v4.f32 [%0], {%1,%2,%3,%4};"
                 :: "l"(p), "f"(f.x * w), "f"(f.y * w), "f"(f.z * w), "f"(f.w * w)
                 : "memory");
}

template <int HC, bool RELU>
__global__ void fin_k(const float* __restrict__ acc, const float* __restrict__ b,
                      float* __restrict__ out, int total) {
    int i = blockIdx.x * blockDim.x + threadIdx.x;
    if (i >= total) return;
    float v = acc[i] + __ldg(b + (i & (HC - 1)));
    if (RELU) v = v > 0.f ? v : 0.f;
    out[i] = v;
}

// ---------------------------------------------------------------------------
extern "C" void kernel_launch(void* const* d_in, const int* in_sizes, int n_in,
                              void* d_out, int out_size) {
    const float* x   = (const float*)d_in[0];
    const void*  ei  = d_in[1];
    const float* W0  = (const float*)d_in[2];
    const float* as0 = (const float*)d_in[3];
    const float* ad0 = (const float*)d_in[4];
    const float* b0  = (const float*)d_in[5];
    const float* W1  = (const float*)d_in[6];
    const float* as1 = (const float*)d_in[7];
    const float* ad1 = (const float*)d_in[8];
    const float* b1  = (const float*)d_in[9];
    const float* W2  = (const float*)d_in[10];
    const float* as2 = (const float*)d_in[11];
    const float* ad2 = (const float*)d_in[12];
    const float* b2  = (const float*)d_in[13];
    float* out = (float*)d_out;

    int N = in_sizes[0] / 128;
    int E = in_sizes[1] / 2;
    int ET = E + N;

    float *feat, *inb, *acc, *asb, *adb, *db, *exb;
    int *srcp, *dstp;
    cudaGetSymbolAddress((void**)&feat, g_feat);
    cudaGetSymbolAddress((void**)&inb,  g_in);
    cudaGetSymbolAddress((void**)&acc,  g_acc);
    cudaGetSymbolAddress((void**)&asb,  g_as);
    cudaGetSymbolAddress((void**)&adb,  g_ad);
    cudaGetSymbolAddress((void**)&db,   g_den);
    cudaGetSymbolAddress((void**)&exb,  g_ex);
    cudaGetSymbolAddress((void**)&srcp, g_src);
    cudaGetSymbolAddress((void**)&dstp, g_dst);

    const int TB = 256;
    int gemmGrid = (N + 127) / 128;

    detect_k<<<1, 1>>>((const unsigned int*)ei);
    decode_k<<<(ET + TB - 1) / TB, TB>>>(ei, E, ET, srcp, dstp);

    // ---------------- Layer 0 ----------------
    gemm_k<128, 4><<<gemmGrid, TB>>>(x, W0, feat, as0, ad0, asb, adb, N);
    init_k<<<(N * 128 + TB - 1) / TB, TB>>>(acc, db, N * 128, N * 4);
    pass2_v4_k<<<(ET + TB - 1) / TB, TB>>>(srcp, dstp, ET, asb, adb, db, exb);
    pass3_128_k<<<((long)ET * 32 + TB - 1) / TB, TB>>>(srcp, dstp, ET, feat, exb, db, acc);
    fin_k<128, true><<<(N * 128 + TB - 1) / TB, TB>>>(acc, b0, inb, N * 128);

    // ---------------- Layer 1 ----------------
    gemm_k<128, 4><<<gemmGrid, TB>>>(inb, W1, feat, as1, ad1, asb, adb, N);
    init_k<<<(N * 128 + TB - 1) / TB, TB>>>(acc, db, N * 128, N * 4);
    pass2_v4_k<<<(ET + TB - 1) / TB, TB>>>(srcp, dstp, ET, asb, adb, db, exb);
    pass3_128_k<<<((long)ET * 32 + TB - 1) / TB, TB>>>(srcp, dstp, ET, feat, exb, db, acc);
    fin_k<128, true><<<(N * 128 + TB - 1) / TB, TB>>>(acc, b1, inb, N * 128);

    // ---------------- Layer 2 ----------------
    gemm_k<64, 1><<<gemmGrid, TB>>>(inb, W2, feat, as2, ad2, asb, adb, N);
    init_k<<<(N * 64 + TB - 1) / TB, TB>>>(acc, db, N * 64, N);
    pass2_s_k<<<(ET + TB - 1) / TB, TB>>>(srcp, dstp, ET, asb, adb, db, exb);
    pass3_64_k<<<((long)ET * 16 + TB - 1) / TB, TB>>>(srcp, dstp, ET, feat, exb, db, acc);
    fin_k<64, false><<<(N * 64 + TB - 1) / TB, TB>>>(acc, b2, out, N * 64);
}

// round 5
// speedup vs baseline: 1.7871x; 1.3867x over previous
#include <cuda_runtime.h>
#include <cstdint>

// ---------------------------------------------------------------------------
// GAT encoder, 3 layers. Round 5 (rebench of round-4 design after infra fail):
// CSR-based atomic-free aggregation.
// Per layer: gemm(+alpha epilogue) -> agg (den + weighted sum + bias + relu).
// One-time: edge decode + CSR build (hist, scan, scatter).
// ---------------------------------------------------------------------------

#define MAXN 50000
#define MAXE 800000
#define MAXET (MAXE + MAXN)

__device__ __align__(16) float g_feat[MAXN * 128];
__device__ __align__(16) float g_in  [MAXN * 128];
__device__ __align__(16) float g_as  [MAXN * 4];
__device__ __align__(16) float g_ad  [MAXN * 4];
__device__ int g_src [MAXET];
__device__ int g_dst [MAXET];
__device__ int g_csrc[MAXET];
__device__ int g_cnt [MAXN];
__device__ int g_fill[MAXN];
__device__ int g_rowptr[MAXN + 1];
__device__ int g_is64;

// ---------------------------------------------------------------------------
__global__ void detect_k(const unsigned int* __restrict__ raw) {
    unsigned int o = 0;
#pragma unroll
    for (int j = 1; j < 128; j += 2) o |= raw[j];
    g_is64 = (o == 0u) ? 1 : 0;
}

__global__ void zero_k(int* __restrict__ cnt, int* __restrict__ fill, int N) {
    int i = blockIdx.x * blockDim.x + threadIdx.x;
    if (i < N) { cnt[i] = 0; fill[i] = 0; }
}

__global__ void decode_hist_k(const void* __restrict__ raw, int E, int ET,
                              int* __restrict__ src, int* __restrict__ dst,
                              int* __restrict__ cnt) {
    int e = blockIdx.x * blockDim.x + threadIdx.x;
    if (e >= ET) return;
    int s, d;
    if (e < E) {
        if (g_is64) {
            const long long* p = (const long long*)raw;
            s = (int)p[e];
            d = (int)p[E + e];
        } else {
            const int* p = (const int*)raw;
            s = p[e];
            d = p[E + e];
        }
    } else {
        s = d = e - E;
    }
    src[e] = s;
    dst[e] = d;
    atomicAdd(&cnt[d], 1);
}

// Single-block exclusive scan (N up to MAXN), 1024 threads.
__global__ void scan_k(const int* __restrict__ cnt, int* __restrict__ rowptr, int N) {
    __shared__ int sh[1024];
    __shared__ int carry;
    int tid = threadIdx.x;
    if (tid == 0) carry = 0;
    __syncthreads();
    for (int base = 0; base < N; base += 1024) {
        int idx = base + tid;
        int v = (idx < N) ? cnt[idx] : 0;
        sh[tid] = v;
        __syncthreads();
        for (int off = 1; off < 1024; off <<= 1) {
            int t = (tid >= off) ? sh[tid - off] : 0;
            __syncthreads();
            sh[tid] += t;
            __syncthreads();
        }
        int c = carry;
        if (idx < N) rowptr[idx] = c + sh[tid] - v;
        __syncthreads();
        if (tid == 0) carry = c + sh[1023];
        __syncthreads();
    }
    if (tid == 0) rowptr[N] = carry;
}

__global__ void scatter_k(const int* __restrict__ src, const int* __restrict__ dst,
                          int ET, const int* __restrict__ rowptr,
                          int* __restrict__ fill, int* __restrict__ csrc) {
    int e = blockIdx.x * blockDim.x + threadIdx.x;
    if (e >= ET) return;
    int d = dst[e];
    int pos = rowptr[d] + atomicAdd(&fill[d], 1);
    csrc[pos] = src[e];
}

// ---------------------------------------------------------------------------
// GEMM + fused alpha epilogue.
// ---------------------------------------------------------------------------
template <int NC, int HH>
__global__ __launch_bounds__(256) void gemm_k(const float* __restrict__ X,
                                              const float* __restrict__ W,
                                              float* __restrict__ O,
                                              const float* __restrict__ avs,
                                              const float* __restrict__ avd,
                                              float* __restrict__ os,
                                              float* __restrict__ od, int M) {
    constexpr int K = 128, KCH = 32, ROWS = 128;
    constexpr int CG = NC / 4;
    constexpr int C4 = CG / 4;
    __shared__ float  Xs[ROWS][KCH + 1];
    __shared__ float4 Ws[KCH][NC / 4];

    int tid = threadIdx.x;
    int cg = tid >> 6;
    int r  = tid & 63;
    int rowbase = blockIdx.x * ROWS;

    float4 aA[C4], aB[C4];
#pragma unroll
    for (int j = 0; j < C4; j++) {
        aA[j] = make_float4(0.f, 0.f, 0.f, 0.f);
        aB[j] = make_float4(0.f, 0.f, 0.f, 0.f);
    }

    for (int kb = 0; kb < K; kb += KCH) {
        for (int i = tid; i < ROWS * (KCH / 4); i += 256) {
            int rr = i >> 3, q = i & 7;
            int gr = rowbase + rr;
            float4 v = make_float4(0.f, 0.f, 0.f, 0.f);
            if (gr < M)
                v = *reinterpret_cast<const float4*>(X + (size_t)gr * K + kb + q * 4);
            Xs[rr][q * 4 + 0] = v.x;
            Xs[rr][q * 4 + 1] = v.y;
            Xs[rr][q * 4 + 2] = v.z;
            Xs[rr][q * 4 + 3] = v.w;
        }
        for (int i = tid; i < KCH * (NC / 4); i += 256) {
            int kk = i / (NC / 4), q = i % (NC / 4);
            Ws[kk][q] = *reinterpret_cast<const float4*>(W + (size_t)(kb + kk) * NC + q * 4);
        }
        __syncthreads();
#pragma unroll 4
        for (int kk = 0; kk < KCH; kk++) {
            float xa = Xs[r][kk];
            float xb = Xs[r + 64][kk];
#pragma unroll
            for (int j = 0; j < C4; j++) {
                float4 w = Ws[kk][cg * C4 + j];
                aA[j].x += xa * w.x; aA[j].y += xa * w.y;
                aA[j].z += xa * w.z; aA[j].w += xa * w.w;
                aB[j].x += xb * w.x; aB[j].y += xb * w.y;
                aB[j].z += xb * w.z; aB[j].w += xb * w.w;
            }
        }
        __syncthreads();
    }

    int rowA = rowbase + r, rowB = rowbase + r + 64;
    if (rowA < M) {
#pragma unroll
        for (int j = 0; j < C4; j++)
            *reinterpret_cast<float4*>(O + (size_t)rowA * NC + cg * CG + j * 4) = aA[j];
    }
    if (rowB < M) {
#pragma unroll
        for (int j = 0; j < C4; j++)
            *reinterpret_cast<float4*>(O + (size_t)rowB * NC + cg * CG + j * 4) = aB[j];
    }

    float sA = 0.f, dA = 0.f, sB = 0.f, dB = 0.f;
#pragma unroll
    for (int j = 0; j < C4; j++) {
        float4 vs = *reinterpret_cast<const float4*>(avs + cg * CG + j * 4);
        float4 vd = *reinterpret_cast<const float4*>(avd + cg * CG + j * 4);
        sA += aA[j].x * vs.x + aA[j].y * vs.y + aA[j].z * vs.z + aA[j].w * vs.w;
        dA += aA[j].x * vd.x + aA[j].y * vd.y + aA[j].z * vd.z + aA[j].w * vd.w;
        sB += aB[j].x * vs.x + aB[j].y * vs.y + aB[j].z * vs.z + aB[j].w * vs.w;
        dB += aB[j].x * vd.x + aB[j].y * vd.y + aB[j].z * vd.z + aB[j].w * vd.w;
    }

    if (HH == 4) {
        if (rowA < M) { os[rowA * 4 + cg] = sA; od[rowA * 4 + cg] = dA; }
        if (rowB < M) { os[rowB * 4 + cg] = sB; od[rowB * 4 + cg] = dB; }
    } else {
        __shared__ float4 red[64][4];
        red[r][cg] = make_float4(sA, dA, sB, dB);
        __syncthreads();
        if (cg == 0) {
            float4 t0 = red[r][0], t1 = red[r][1], t2 = red[r][2], t3 = red[r][3];
            if (rowA < M) { os[rowA] = t0.x + t1.x + t2.x + t3.x; od[rowA] = t0.y + t1.y + t2.y + t3.y; }
            if (rowB < M) { os[rowB] = t0.z + t1.z + t2.z + t3.z; od[rowB] = t0.w + t1.w + t2.w + t3.w; }
        }
    }
}

// ---------------------------------------------------------------------------
// CSR aggregation, HC=128 (H=4,C=32). Warp per dst node.
// Lane l: head h = l>>3, float4 slot l of the 128-wide row.
// Sweep 1: den[h]; sweep 2: sum ex * feat[src]; epilogue: /den + bias, relu.
// ---------------------------------------------------------------------------
__global__ __launch_bounds__(256) void agg128_k(const int* __restrict__ rowptr,
                                                const int* __restrict__ csrc,
                                                const float* __restrict__ feat,
                                                const float* __restrict__ as_,
                                                const float* __restrict__ ad_,
                                                const float* __restrict__ b,
                                                float* __restrict__ out, int N) {
    int gt = blockIdx.x * blockDim.x + threadIdx.x;
    int n = gt >> 5;
    int lane = gt & 31;
    if (n >= N) return;
    int h = lane >> 3;
    float adv = __ldg(ad_ + n * 4 + h);
    int p0 = __ldg(rowptr + n), p1 = __ldg(rowptr + n + 1);

    float den = 0.f;
    for (int i = p0; i < p1; i++) {
        int s = __ldg(csrc + i);
        float v = __ldg(as_ + s * 4 + h) + adv;
        v = v > 0.f ? v : 0.2f * v;
        den += __expf(v);
    }

    float4 acc = make_float4(0.f, 0.f, 0.f, 0.f);
    for (int i = p0; i < p1; i++) {
        int s = __ldg(csrc + i);
        float4 f = __ldg(reinterpret_cast<const float4*>(feat) + (size_t)s * 32 + lane);
        float v = __ldg(as_ + s * 4 + h) + adv;
        v = v > 0.f ? v : 0.2f * v;
        float ex = __expf(v);
        acc.x += ex * f.x; acc.y += ex * f.y;
        acc.z += ex * f.z; acc.w += ex * f.w;
    }

    float w = 1.f / (den + 1e-16f);
    float4 bb = *reinterpret_cast<const float4*>(b + lane * 4);
    float4 o;
    o.x = fmaxf(acc.x * w + bb.x, 0.f);
    o.y = fmaxf(acc.y * w + bb.y, 0.f);
    o.z = fmaxf(acc.z * w + bb.z, 0.f);
    o.w = fmaxf(acc.w * w + bb.w, 0.f);
    reinterpret_cast<float4*>(out)[(size_t)n * 32 + lane] = o;
}

// CSR aggregation, HC=64 (H=1,C=64), no relu. Warp per node, float2 per lane.
__global__ __launch_bounds__(256) void agg64_k(const int* __restrict__ rowptr,
                                               const int* __restrict__ csrc,
                                               const float* __restrict__ feat,
                                               const float* __restrict__ as_,
                                               const float* __restrict__ ad_,
                                               const float* __restrict__ b,
                                               float* __restrict__ out, int N) {
    int gt = blockIdx.x * blockDim.x + threadIdx.x;
    int n = gt >> 5;
    int lane = gt & 31;
    if (n >= N) return;
    float adv = __ldg(ad_ + n);
    int p0 = __ldg(rowptr + n), p1 = __ldg(rowptr + n + 1);

    float den = 0.f;
    for (int i = p0; i < p1; i++) {
        int s = __ldg(csrc + i);
        float v = __ldg(as_ + s) + adv;
        v = v > 0.f ? v : 0.2f * v;
        den += __expf(v);
    }

    float2 acc = make_float2(0.f, 0.f);
    for (int i = p0; i < p1; i++) {
        int s = __ldg(csrc + i);
        float2 f = __ldg(reinterpret_cast<const float2*>(feat) + (size_t)s * 32 + lane);
        float v = __ldg(as_ + s) + adv;
        v = v > 0.f ? v : 0.2f * v;
        float ex = __expf(v);
        acc.x += ex * f.x; acc.y += ex * f.y;
    }

    float w = 1.f / (den + 1e-16f);
    float2 bb = *reinterpret_cast<const float2*>(b + lane * 2);
    float2 o;
    o.x = acc.x * w + bb.x;
    o.y = acc.y * w + bb.y;
    reinterpret_cast<float2*>(out)[(size_t)n * 32 + lane] = o;
}

// ---------------------------------------------------------------------------
extern "C" void kernel_launch(void* const* d_in, const int* in_sizes, int n_in,
                              void* d_out, int out_size) {
    const float* x   = (const float*)d_in[0];
    const void*  ei  = d_in[1];
    const float* W0  = (const float*)d_in[2];
    const float* as0 = (const float*)d_in[3];
    const float* ad0 = (const float*)d_in[4];
    const float* b0  = (const float*)d_in[5];
    const float* W1  = (const float*)d_in[6];
    const float* as1 = (const float*)d_in[7];
    const float* ad1 = (const float*)d_in[8];
    const float* b1  = (const float*)d_in[9];
    const float* W2  = (const float*)d_in[10];
    const float* as2 = (const float*)d_in[11];
    const float* ad2 = (const float*)d_in[12];
    const float* b2  = (const float*)d_in[13];
    float* out = (float*)d_out;

    int N = in_sizes[0] / 128;
    int E = in_sizes[1] / 2;
    int ET = E + N;

    float *feat, *inb, *asb, *adb;
    int *srcp, *dstp, *csrc, *cnt, *fill, *rowptr;
    cudaGetSymbolAddress((void**)&feat,   g_feat);
    cudaGetSymbolAddress((void**)&inb,    g_in);
    cudaGetSymbolAddress((void**)&asb,    g_as);
    cudaGetSymbolAddress((void**)&adb,    g_ad);
    cudaGetSymbolAddress((void**)&srcp,   g_src);
    cudaGetSymbolAddress((void**)&dstp,   g_dst);
    cudaGetSymbolAddress((void**)&csrc,   g_csrc);
    cudaGetSymbolAddress((void**)&cnt,    g_cnt);
    cudaGetSymbolAddress((void**)&fill,   g_fill);
    cudaGetSymbolAddress((void**)&rowptr, g_rowptr);

    const int TB = 256;
    int gemmGrid = (N + 127) / 128;
    int aggGrid = ((long)N * 32 + TB - 1) / TB;

    // ---- one-time CSR build ----
    detect_k<<<1, 1>>>((const unsigned int*)ei);
    zero_k<<<(N + TB - 1) / TB, TB>>>(cnt, fill, N);
    decode_hist_k<<<(ET + TB - 1) / TB, TB>>>(ei, E, ET, srcp, dstp, cnt);
    scan_k<<<1, 1024>>>(cnt, rowptr, N);
    scatter_k<<<(ET + TB - 1) / TB, TB>>>(srcp, dstp, ET, rowptr, fill, csrc);

    // ---------------- Layer 0 ----------------
    gemm_k<128, 4><<<gemmGrid, TB>>>(x, W0, feat, as0, ad0, asb, adb, N);
    agg128_k<<<aggGrid, TB>>>(rowptr, csrc, feat, asb, adb, b0, inb, N);

    // ---------------- Layer 1 ----------------
    gemm_k<128, 4><<<gemmGrid, TB>>>(inb, W1, feat, as1, ad1, asb, adb, N);
    agg128_k<<<aggGrid, TB>>>(rowptr, csrc, feat, asb, adb, b1, inb, N);

    // ---------------- Layer 2 ----------------
    gemm_k<64, 1><<<gemmGrid, TB>>>(inb, W2, feat, as2, ad2, asb, adb, N);
    agg64_k<<<aggGrid, TB>>>(rowptr, csrc, feat, asb, adb, b2, out, N);
}

// round 7
// speedup vs baseline: 2.1144x; 1.1832x over previous
#include <cuda_runtime.h>
#include <cstdint>

// ---------------------------------------------------------------------------
// GAT encoder, 3 layers. Round 7 (rebench of round-6 after infra fail):
// hierarchical (3-phase) CSR rowptr scan replaces the 82us single-block scan.
// Rest identical to round 5 (390us baseline).
// ---------------------------------------------------------------------------

#define MAXN 50000
#define MAXE 800000
#define MAXET (MAXE + MAXN)

__device__ __align__(16) float g_feat[MAXN * 128];
__device__ __align__(16) float g_in  [MAXN * 128];
__device__ __align__(16) float g_as  [MAXN * 4];
__device__ __align__(16) float g_ad  [MAXN * 4];
__device__ int g_src [MAXET];
__device__ int g_dst [MAXET];
__device__ int g_csrc[MAXET];
__device__ int g_cnt [MAXN];
__device__ int g_fill[MAXN];
__device__ int g_rowptr[MAXN + 1];
__device__ int g_bsum[64];
__device__ int g_is64;

// ---------------------------------------------------------------------------
__global__ void detect_k(const unsigned int* __restrict__ raw) {
    unsigned int o = 0;
#pragma unroll
    for (int j = 1; j < 128; j += 2) o |= raw[j];
    g_is64 = (o == 0u) ? 1 : 0;
}

__global__ void zero_k(int* __restrict__ cnt, int* __restrict__ fill, int N) {
    int i = blockIdx.x * blockDim.x + threadIdx.x;
    if (i < N) { cnt[i] = 0; fill[i] = 0; }
}

__global__ void decode_hist_k(const void* __restrict__ raw, int E, int ET,
                              int* __restrict__ src, int* __restrict__ dst,
                              int* __restrict__ cnt) {
    int e = blockIdx.x * blockDim.x + threadIdx.x;
    if (e >= ET) return;
    int s, d;
    if (e < E) {
        if (g_is64) {
            const long long* p = (const long long*)raw;
            s = (int)p[e];
            d = (int)p[E + e];
        } else {
            const int* p = (const int*)raw;
            s = p[e];
            d = p[E + e];
        }
    } else {
        s = d = e - E;
    }
    src[e] = s;
    dst[e] = d;
    atomicAdd(&cnt[d], 1);
}

// ---------------------------------------------------------------------------
// 3-phase parallel exclusive scan of cnt[0..N) -> rowptr[0..N].
// ---------------------------------------------------------------------------
__device__ __forceinline__ int warp_incl_scan(int v) {
    int lane = threadIdx.x & 31;
#pragma unroll
    for (int o = 1; o < 32; o <<= 1) {
        int t = __shfl_up_sync(0xffffffffu, v, o);
        if (lane >= o) v += t;
    }
    return v;
}

// Phase 1: per-1024-chunk exclusive scan (chunk-local) + per-chunk total.
__global__ __launch_bounds__(1024) void scan1_k(const int* __restrict__ cnt,
                                                int* __restrict__ rowptr,
                                                int* __restrict__ bsum, int N) {
    __shared__ int wsum[32];
    int tid = threadIdx.x;
    int idx = blockIdx.x * 1024 + tid;
    int wid = tid >> 5, lane = tid & 31;
    int v = (idx < N) ? cnt[idx] : 0;
    int inc = warp_incl_scan(v);
    if (lane == 31) wsum[wid] = inc;
    __syncthreads();
    if (wid == 0) {
        int w = wsum[lane];
        wsum[lane] = warp_incl_scan(w);
    }
    __syncthreads();
    int off = (wid > 0) ? wsum[wid - 1] : 0;
    if (idx < N) rowptr[idx] = off + inc - v;   // chunk-local exclusive
    if (tid == 1023) bsum[blockIdx.x] = off + inc;
}

// Phase 2: exclusive scan of block sums (nb <= 64); writes rowptr[N]=total.
__global__ void scan2_k(int* __restrict__ bsum, int nb, int* __restrict__ rowptr, int N) {
    __shared__ int sh[64];
    int tid = threadIdx.x;  // 64 threads
    sh[tid] = (tid < nb) ? bsum[tid] : 0;
    __syncthreads();
    for (int o = 1; o < 64; o <<= 1) {
        int t = (tid >= o) ? sh[tid - o] : 0;
        __syncthreads();
        sh[tid] += t;
        __syncthreads();
    }
    if (tid < nb) bsum[tid] = (tid > 0) ? sh[tid - 1] : 0;
    if (tid == 0) rowptr[N] = sh[nb - 1];
}

// Phase 3: add chunk offsets.
__global__ void scan3_k(int* __restrict__ rowptr, const int* __restrict__ bsum, int N) {
    int idx = blockIdx.x * blockDim.x + threadIdx.x;
    if (idx < N) rowptr[idx] += bsum[idx >> 10];
}

__global__ void scatter_k(const int* __restrict__ src, const int* __restrict__ dst,
                          int ET, const int* __restrict__ rowptr,
                          int* __restrict__ fill, int* __restrict__ csrc) {
    int e = blockIdx.x * blockDim.x + threadIdx.x;
    if (e >= ET) return;
    int d = dst[e];
    int pos = rowptr[d] + atomicAdd(&fill[d], 1);
    csrc[pos] = src[e];
}

// ---------------------------------------------------------------------------
// GEMM + fused alpha epilogue.
// ---------------------------------------------------------------------------
template <int NC, int HH>
__global__ __launch_bounds__(256) void gemm_k(const float* __restrict__ X,
                                              const float* __restrict__ W,
                                              float* __restrict__ O,
                                              const float* __restrict__ avs,
                                              const float* __restrict__ avd,
                                              float* __restrict__ os,
                                              float* __restrict__ od, int M) {
    constexpr int K = 128, KCH = 32, ROWS = 128;
    constexpr int CG = NC / 4;
    constexpr int C4 = CG / 4;
    __shared__ float  Xs[ROWS][KCH + 1];
    __shared__ float4 Ws[KCH][NC / 4];

    int tid = threadIdx.x;
    int cg = tid >> 6;
    int r  = tid & 63;
    int rowbase = blockIdx.x * ROWS;

    float4 aA[C4], aB[C4];
#pragma unroll
    for (int j = 0; j < C4; j++) {
        aA[j] = make_float4(0.f, 0.f, 0.f, 0.f);
        aB[j] = make_float4(0.f, 0.f, 0.f, 0.f);
    }

    for (int kb = 0; kb < K; kb += KCH) {
        for (int i = tid; i < ROWS * (KCH / 4); i += 256) {
            int rr = i >> 3, q = i & 7;
            int gr = rowbase + rr;
            float4 v = make_float4(0.f, 0.f, 0.f, 0.f);
            if (gr < M)
                v = *reinterpret_cast<const float4*>(X + (size_t)gr * K + kb + q * 4);
            Xs[rr][q * 4 + 0] = v.x;
            Xs[rr][q * 4 + 1] = v.y;
            Xs[rr][q * 4 + 2] = v.z;
            Xs[rr][q * 4 + 3] = v.w;
        }
        for (int i = tid; i < KCH * (NC / 4); i += 256) {
            int kk = i / (NC / 4), q = i % (NC / 4);
            Ws[kk][q] = *reinterpret_cast<const float4*>(W + (size_t)(kb + kk) * NC + q * 4);
        }
        __syncthreads();
#pragma unroll 4
        for (int kk = 0; kk < KCH; kk++) {
            float xa = Xs[r][kk];
            float xb = Xs[r + 64][kk];
#pragma unroll
            for (int j = 0; j < C4; j++) {
                float4 w = Ws[kk][cg * C4 + j];
                aA[j].x += xa * w.x; aA[j].y += xa * w.y;
                aA[j].z += xa * w.z; aA[j].w += xa * w.w;
                aB[j].x += xb * w.x; aB[j].y += xb * w.y;
                aB[j].z += xb * w.z; aB[j].w += xb * w.w;
            }
        }
        __syncthreads();
    }

    int rowA = rowbase + r, rowB = rowbase + r + 64;
    if (rowA < M) {
#pragma unroll
        for (int j = 0; j < C4; j++)
            *reinterpret_cast<float4*>(O + (size_t)rowA * NC + cg * CG + j * 4) = aA[j];
    }
    if (rowB < M) {
#pragma unroll
        for (int j = 0; j < C4; j++)
            *reinterpret_cast<float4*>(O + (size_t)rowB * NC + cg * CG + j * 4) = aB[j];
    }

    float sA = 0.f, dA = 0.f, sB = 0.f, dB = 0.f;
#pragma unroll
    for (int j = 0; j < C4; j++) {
        float4 vs = *reinterpret_cast<const float4*>(avs + cg * CG + j * 4);
        float4 vd = *reinterpret_cast<const float4*>(avd + cg * CG + j * 4);
        sA += aA[j].x * vs.x + aA[j].y * vs.y + aA[j].z * vs.z + aA[j].w * vs.w;
        dA += aA[j].x * vd.x + aA[j].y * vd.y + aA[j].z * vd.z + aA[j].w * vd.w;
        sB += aB[j].x * vs.x + aB[j].y * vs.y + aB[j].z * vs.z + aB[j].w * vs.w;
        dB += aB[j].x * vd.x + aB[j].y * vd.y + aB[j].z * vd.z + aB[j].w * vd.w;
    }

    if (HH == 4) {
        if (rowA < M) { os[rowA * 4 + cg] = sA; od[rowA * 4 + cg] = dA; }
        if (rowB < M) { os[rowB * 4 + cg] = sB; od[rowB * 4 + cg] = dB; }
    } else {
        __shared__ float4 red[64][4];
        red[r][cg] = make_float4(sA, dA, sB, dB);
        __syncthreads();
        if (cg == 0) {
            float4 t0 = red[r][0], t1 = red[r][1], t2 = red[r][2], t3 = red[r][3];
            if (rowA < M) { os[rowA] = t0.x + t1.x + t2.x + t3.x; od[rowA] = t0.y + t1.y + t2.y + t3.y; }
            if (rowB < M) { os[rowB] = t0.z + t1.z + t2.z + t3.z; od[rowB] = t0.w + t1.w + t2.w + t3.w; }
        }
    }
}

// ---------------------------------------------------------------------------
// CSR aggregation, HC=128 (H=4,C=32). Warp per dst node.
// ---------------------------------------------------------------------------
__global__ __launch_bounds__(256) void agg128_k(const int* __restrict__ rowptr,
                                                const int* __restrict__ csrc,
                                                const float* __restrict__ feat,
                                                const float* __restrict__ as_,
                                                const float* __restrict__ ad_,
                                                const float* __restrict__ b,
                                                float* __restrict__ out, int N) {
    int gt = blockIdx.x * blockDim.x + threadIdx.x;
    int n = gt >> 5;
    int lane = gt & 31;
    if (n >= N) return;
    int h = lane >> 3;
    float adv = __ldg(ad_ + n * 4 + h);
    int p0 = __ldg(rowptr + n), p1 = __ldg(rowptr + n + 1);

    float den = 0.f;
    for (int i = p0; i < p1; i++) {
        int s = __ldg(csrc + i);
        float v = __ldg(as_ + s * 4 + h) + adv;
        v = v > 0.f ? v : 0.2f * v;
        den += __expf(v);
    }

    float4 acc = make_float4(0.f, 0.f, 0.f, 0.f);
    for (int i = p0; i < p1; i++) {
        int s = __ldg(csrc + i);
        float4 f = __ldg(reinterpret_cast<const float4*>(feat) + (size_t)s * 32 + lane);
        float v = __ldg(as_ + s * 4 + h) + adv;
        v = v > 0.f ? v : 0.2f * v;
        float ex = __expf(v);
        acc.x += ex * f.x; acc.y += ex * f.y;
        acc.z += ex * f.z; acc.w += ex * f.w;
    }

    float w = 1.f / (den + 1e-16f);
    float4 bb = *reinterpret_cast<const float4*>(b + lane * 4);
    float4 o;
    o.x = fmaxf(acc.x * w + bb.x, 0.f);
    o.y = fmaxf(acc.y * w + bb.y, 0.f);
    o.z = fmaxf(acc.z * w + bb.z, 0.f);
    o.w = fmaxf(acc.w * w + bb.w, 0.f);
    reinterpret_cast<float4*>(out)[(size_t)n * 32 + lane] = o;
}

// CSR aggregation, HC=64 (H=1,C=64), no relu.
__global__ __launch_bounds__(256) void agg64_k(const int* __restrict__ rowptr,
                                               const int* __restrict__ csrc,
                                               const float* __restrict__ feat,
                                               const float* __restrict__ as_,
                                               const float* __restrict__ ad_,
                                               const float* __restrict__ b,
                                               float* __restrict__ out, int N) {
    int gt = blockIdx.x * blockDim.x + threadIdx.x;
    int n = gt >> 5;
    int lane = gt & 31;
    if (n >= N) return;
    float adv = __ldg(ad_ + n);
    int p0 = __ldg(rowptr + n), p1 = __ldg(rowptr + n + 1);

    float den = 0.f;
    for (int i = p0; i < p1; i++) {
        int s = __ldg(csrc + i);
        float v = __ldg(as_ + s) + adv;
        v = v > 0.f ? v : 0.2f * v;
        den += __expf(v);
    }

    float2 acc = make_float2(0.f, 0.f);
    for (int i = p0; i < p1; i++) {
        int s = __ldg(csrc + i);
        float2 f = __ldg(reinterpret_cast<const float2*>(feat) + (size_t)s * 32 + lane);
        float v = __ldg(as_ + s) + adv;
        v = v > 0.f ? v : 0.2f * v;
        float ex = __expf(v);
        acc.x += ex * f.x; acc.y += ex * f.y;
    }

    float w = 1.f / (den + 1e-16f);
    float2 bb = *reinterpret_cast<const float2*>(b + lane * 2);
    float2 o;
    o.x = acc.x * w + bb.x;
    o.y = acc.y * w + bb.y;
    reinterpret_cast<float2*>(out)[(size_t)n * 32 + lane] = o;
}

// ---------------------------------------------------------------------------
extern "C" void kernel_launch(void* const* d_in, const int* in_sizes, int n_in,
                              void* d_out, int out_size) {
    const float* x   = (const float*)d_in[0];
    const void*  ei  = d_in[1];
    const float* W0  = (const float*)d_in[2];
    const float* as0 = (const float*)d_in[3];
    const float* ad0 = (const float*)d_in[4];
    const float* b0  = (const float*)d_in[5];
    const float* W1  = (const float*)d_in[6];
    const float* as1 = (const float*)d_in[7];
    const float* ad1 = (const float*)d_in[8];
    const float* b1  = (const float*)d_in[9];
    const float* W2  = (const float*)d_in[10];
    const float* as2 = (const float*)d_in[11];
    const float* ad2 = (const float*)d_in[12];
    const float* b2  = (const float*)d_in[13];
    float* out = (float*)d_out;

    int N = in_sizes[0] / 128;
    int E = in_sizes[1] / 2;
    int ET = E + N;

    float *feat, *inb, *asb, *adb;
    int *srcp, *dstp, *csrc, *cnt, *fill, *rowptr, *bsum;
    cudaGetSymbolAddress((void**)&feat,   g_feat);
    cudaGetSymbolAddress((void**)&inb,    g_in);
    cudaGetSymbolAddress((void**)&asb,    g_as);
    cudaGetSymbolAddress((void**)&adb,    g_ad);
    cudaGetSymbolAddress((void**)&srcp,   g_src);
    cudaGetSymbolAddress((void**)&dstp,   g_dst);
    cudaGetSymbolAddress((void**)&csrc,   g_csrc);
    cudaGetSymbolAddress((void**)&cnt,    g_cnt);
    cudaGetSymbolAddress((void**)&fill,   g_fill);
    cudaGetSymbolAddress((void**)&rowptr, g_rowptr);
    cudaGetSymbolAddress((void**)&bsum,   g_bsum);

    const int TB = 256;
    int gemmGrid = (N + 127) / 128;
    int aggGrid = ((long)N * 32 + TB - 1) / TB;
    int nchunk = (N + 1023) / 1024;

    // ---- one-time CSR build ----
    detect_k<<<1, 1>>>((const unsigned int*)ei);
    zero_k<<<(N + TB - 1) / TB, TB>>>(cnt, fill, N);
    decode_hist_k<<<(ET + TB - 1) / TB, TB>>>(ei, E, ET, srcp, dstp, cnt);
    scan1_k<<<nchunk, 1024>>>(cnt, rowptr, bsum, N);
    scan2_k<<<1, 64>>>(bsum, nchunk, rowptr, N);
    scan3_k<<<(N + TB - 1) / TB, TB>>>(rowptr, bsum, N);
    scatter_k<<<(ET + TB - 1) / TB, TB>>>(srcp, dstp, ET, rowptr, fill, csrc);

    // ---------------- Layer 0 ----------------
    gemm_k<128, 4><<<gemmGrid, TB>>>(x, W0, feat, as0, ad0, asb, adb, N);
    agg128_k<<<aggGrid, TB>>>(rowptr, csrc, feat, asb, adb, b0, inb, N);

    // ---------------- Layer 1 ----------------
    gemm_k<128, 4><<<gemmGrid, TB>>>(inb, W1, feat, as1, ad1, asb, adb, N);
    agg128_k<<<aggGrid, TB>>>(rowptr, csrc, feat, asb, adb, b1, inb, N);

    // ---------------- Layer 2 ----------------
    gemm_k<64, 1><<<gemmGrid, TB>>>(inb, W2, feat, as2, ad2, asb, adb, N);
    agg64_k<<<aggGrid, TB>>>(rowptr, csrc, feat, asb, adb, b2, out, N);
}

// round 9
// speedup vs baseline: 2.6805x; 1.2677x over previous
#include <cuda_runtime.h>
#include <cstdint>

// ---------------------------------------------------------------------------
// GAT encoder, 3 layers. Round 9 (rebench of round-8 after infra fail):
// tensor-core GEMM (mma.sync tf32, 3-term precision split) + fused alpha
// epilogue. CSR build + warp-per-node aggregation unchanged from round 7.
// ---------------------------------------------------------------------------

#define MAXN 50000
#define MAXE 800000
#define MAXET (MAXE + MAXN)

__device__ __align__(16) float g_feat[MAXN * 128];
__device__ __align__(16) float g_in  [MAXN * 128];
__device__ __align__(16) float g_as  [MAXN * 4];
__device__ __align__(16) float g_ad  [MAXN * 4];
__device__ int g_src [MAXET];
__device__ int g_dst [MAXET];
__device__ int g_csrc[MAXET];
__device__ int g_cnt [MAXN];
__device__ int g_fill[MAXN];
__device__ int g_rowptr[MAXN + 1];
__device__ int g_bsum[64];
__device__ int g_is64;

// ---------------------------------------------------------------------------
__global__ void detect_k(const unsigned int* __restrict__ raw) {
    unsigned int o = 0;
#pragma unroll
    for (int j = 1; j < 128; j += 2) o |= raw[j];
    g_is64 = (o == 0u) ? 1 : 0;
}

__global__ void zero_k(int* __restrict__ cnt, int* __restrict__ fill, int N) {
    int i = blockIdx.x * blockDim.x + threadIdx.x;
    if (i < N) { cnt[i] = 0; fill[i] = 0; }
}

__global__ void decode_hist_k(const void* __restrict__ raw, int E, int ET,
                              int* __restrict__ src, int* __restrict__ dst,
                              int* __restrict__ cnt) {
    int e = blockIdx.x * blockDim.x + threadIdx.x;
    if (e >= ET) return;
    int s, d;
    if (e < E) {
        if (g_is64) {
            const long long* p = (const long long*)raw;
            s = (int)p[e];
            d = (int)p[E + e];
        } else {
            const int* p = (const int*)raw;
            s = p[e];
            d = p[E + e];
        }
    } else {
        s = d = e - E;
    }
    src[e] = s;
    dst[e] = d;
    atomicAdd(&cnt[d], 1);
}

__device__ __forceinline__ int warp_incl_scan(int v) {
    int lane = threadIdx.x & 31;
#pragma unroll
    for (int o = 1; o < 32; o <<= 1) {
        int t = __shfl_up_sync(0xffffffffu, v, o);
        if (lane >= o) v += t;
    }
    return v;
}

__global__ __launch_bounds__(1024) void scan1_k(const int* __restrict__ cnt,
                                                int* __restrict__ rowptr,
                                                int* __restrict__ bsum, int N) {
    __shared__ int wsum[32];
    int tid = threadIdx.x;
    int idx = blockIdx.x * 1024 + tid;
    int wid = tid >> 5, lane = tid & 31;
    int v = (idx < N) ? cnt[idx] : 0;
    int inc = warp_incl_scan(v);
    if (lane == 31) wsum[wid] = inc;
    __syncthreads();
    if (wid == 0) {
        int w = wsum[lane];
        wsum[lane] = warp_incl_scan(w);
    }
    __syncthreads();
    int off = (wid > 0) ? wsum[wid - 1] : 0;
    if (idx < N) rowptr[idx] = off + inc - v;
    if (tid == 1023) bsum[blockIdx.x] = off + inc;
}

__global__ void scan2_k(int* __restrict__ bsum, int nb, int* __restrict__ rowptr, int N) {
    __shared__ int sh[64];
    int tid = threadIdx.x;
    sh[tid] = (tid < nb) ? bsum[tid] : 0;
    __syncthreads();
    for (int o = 1; o < 64; o <<= 1) {
        int t = (tid >= o) ? sh[tid - o] : 0;
        __syncthreads();
        sh[tid] += t;
        __syncthreads();
    }
    if (tid < nb) bsum[tid] = (tid > 0) ? sh[tid - 1] : 0;
    if (tid == 0) rowptr[N] = sh[nb - 1];
}

__global__ void scan3_k(int* __restrict__ rowptr, const int* __restrict__ bsum, int N) {
    int idx = blockIdx.x * blockDim.x + threadIdx.x;
    if (idx < N) rowptr[idx] += bsum[idx >> 10];
}

__global__ void scatter_k(const int* __restrict__ src, const int* __restrict__ dst,
                          int ET, const int* __restrict__ rowptr,
                          int* __restrict__ fill, int* __restrict__ csrc) {
    int e = blockIdx.x * blockDim.x + threadIdx.x;
    if (e >= ET) return;
    int d = dst[e];
    int pos = rowptr[d] + atomicAdd(&fill[d], 1);
    csrc[pos] = src[e];
}

// ---------------------------------------------------------------------------
// tf32 helpers
// ---------------------------------------------------------------------------
__device__ __forceinline__ uint32_t f2tf(float f) {
    uint32_t u;
    asm("cvt.rna.tf32.f32 %0, %1;" : "=r"(u) : "f"(f));
    return u;
}

__device__ __forceinline__ void mma8(float4& d, const uint32_t* a, const uint32_t* b) {
    asm volatile(
        "mma.sync.aligned.m16n8k8.row.col.f32.tf32.tf32.f32 "
        "{%0,%1,%2,%3}, {%4,%5,%6,%7}, {%8,%9}, {%0,%1,%2,%3};"
        : "+f"(d.x), "+f"(d.y), "+f"(d.z), "+f"(d.w)
        : "r"(a[0]), "r"(a[1]), "r"(a[2]), "r"(a[3]), "r"(b[0]), "r"(b[1]));
}

// ---------------------------------------------------------------------------
// Tensor-core GEMM: O[M,NC] = X[M,128] @ W[128,NC], fused alpha epilogue.
// Block: 256 thr, 128-row tile. Warp w: rowgroup rg=w/2 (32 rows, 2 m16
// tiles), colgroup cg2=w%2 (NC/2 cols, NT n8 tiles). K in 2 chunks of 64.
// 3-term tf32 split per tile: D += Ahi*Bhi + Ahi*Blo + Alo*Bhi.
// ---------------------------------------------------------------------------
template <int NC, int HH>
__global__ __launch_bounds__(256) void gemm_tc(const float* __restrict__ X,
                                               const float* __restrict__ W,
                                               float* __restrict__ O,
                                               const float* __restrict__ avs,
                                               const float* __restrict__ avd,
                                               float* __restrict__ os,
                                               float* __restrict__ od, int M) {
    constexpr int KC = 64;
    constexpr int XSS = 68;        // X smem row stride (64 + 4 pad)
    constexpr int WSS = NC + 4;    // W smem row stride
    constexpr int CGW = NC / 2;    // cols per warp
    constexpr int NT  = CGW / 8;   // n8 tiles per warp
    constexpr int LH  = (HH == 4) ? 2 : 1;  // local heads per warp

    extern __shared__ float smem[];
    float* Xs = smem;                   // 128 * XSS
    float* Ws = smem + 128 * XSS;       // KC * WSS

    int tid = threadIdx.x;
    int warp = tid >> 5, lane = tid & 31;
    int rg = warp >> 1, cg2 = warp & 1;
    int lr = lane >> 2, lc = lane & 3;
    int rowbase = blockIdx.x * 128;

    float4 acc[2][NT];
#pragma unroll
    for (int mt = 0; mt < 2; mt++)
#pragma unroll
        for (int nt = 0; nt < NT; nt++)
            acc[mt][nt] = make_float4(0.f, 0.f, 0.f, 0.f);

    for (int kb = 0; kb < 128; kb += KC) {
        __syncthreads();
        // stage X tile: 128 rows x 64 k
#pragma unroll
        for (int i = 0; i < 8; i++) {
            int t = tid + i * 256;
            int row = t >> 4, q = t & 15;
            float4 v = make_float4(0.f, 0.f, 0.f, 0.f);
            if (rowbase + row < M)
                v = *reinterpret_cast<const float4*>(X + (size_t)(rowbase + row) * 128 + kb + q * 4);
            reinterpret_cast<float4*>(Xs + row * XSS)[q] = v;
        }
        // stage W tile: 64 k x NC
#pragma unroll
        for (int i = 0; i < (KC * NC / 4) / 256; i++) {
            int t = tid + i * 256;
            int k = t / (NC / 4), q = t % (NC / 4);
            float4 v = *reinterpret_cast<const float4*>(W + (size_t)(kb + k) * NC + q * 4);
            reinterpret_cast<float4*>(Ws + k * WSS)[q] = v;
        }
        __syncthreads();

#pragma unroll
        for (int kc = 0; kc < KC / 8; kc++) {
            uint32_t ah[2][4], al[2][4];
#pragma unroll
            for (int mt = 0; mt < 2; mt++) {
                const float* ab = Xs + (rg * 32 + mt * 16 + lr) * XSS + kc * 8 + lc;
                float f0 = ab[0];
                float f1 = ab[8 * XSS];
                float f2 = ab[4];
                float f3 = ab[8 * XSS + 4];
                ah[mt][0] = f2tf(f0); al[mt][0] = f2tf(f0 - __uint_as_float(ah[mt][0]));
                ah[mt][1] = f2tf(f1); al[mt][1] = f2tf(f1 - __uint_as_float(ah[mt][1]));
                ah[mt][2] = f2tf(f2); al[mt][2] = f2tf(f2 - __uint_as_float(ah[mt][2]));
                ah[mt][3] = f2tf(f3); al[mt][3] = f2tf(f3 - __uint_as_float(ah[mt][3]));
            }
#pragma unroll
            for (int nt = 0; nt < NT; nt++) {
                const float* bb = Ws + (kc * 8 + lc) * WSS + cg2 * CGW + nt * 8 + lr;
                float g0 = bb[0];
                float g1 = bb[4 * WSS];
                uint32_t bh[2], bl[2];
                bh[0] = f2tf(g0); bl[0] = f2tf(g0 - __uint_as_float(bh[0]));
                bh[1] = f2tf(g1); bl[1] = f2tf(g1 - __uint_as_float(bh[1]));
#pragma unroll
                for (int mt = 0; mt < 2; mt++) {
                    mma8(acc[mt][nt], ah[mt], bh);
                    mma8(acc[mt][nt], ah[mt], bl);
                    mma8(acc[mt][nt], al[mt], bh);
                }
            }
        }
    }

    // ---- epilogue: store O + fused alpha dots ----
    float sA[2][2][LH], sD[2][2][LH];
#pragma unroll
    for (int mt = 0; mt < 2; mt++)
#pragma unroll
        for (int rs = 0; rs < 2; rs++)
#pragma unroll
            for (int lh = 0; lh < LH; lh++) { sA[mt][rs][lh] = 0.f; sD[mt][rs][lh] = 0.f; }

#pragma unroll
    for (int mt = 0; mt < 2; mt++) {
        int r0 = rowbase + rg * 32 + mt * 16 + lr;
#pragma unroll
        for (int nt = 0; nt < NT; nt++) {
            int col = cg2 * CGW + nt * 8 + 2 * lc;
            float4 d = acc[mt][nt];
            float av0 = __ldg(avs + col), av1 = __ldg(avs + col + 1);
            float dv0 = __ldg(avd + col), dv1 = __ldg(avd + col + 1);
            int lh = (HH == 4) ? (nt / (NT / 2)) : 0;
            sA[mt][0][lh] += d.x * av0 + d.y * av1;
            sD[mt][0][lh] += d.x * dv0 + d.y * dv1;
            sA[mt][1][lh] += d.z * av0 + d.w * av1;
            sD[mt][1][lh] += d.z * dv0 + d.w * dv1;
            if (r0 < M)
                *reinterpret_cast<float2*>(O + (size_t)r0 * NC + col) = make_float2(d.x, d.y);
            if (r0 + 8 < M)
                *reinterpret_cast<float2*>(O + (size_t)(r0 + 8) * NC + col) = make_float2(d.z, d.w);
        }
    }

    // reduce partial dots over the 4-lane column group
#pragma unroll
    for (int mt = 0; mt < 2; mt++)
#pragma unroll
        for (int rs = 0; rs < 2; rs++)
#pragma unroll
            for (int lh = 0; lh < LH; lh++) {
                float a = sA[mt][rs][lh], d = sD[mt][rs][lh];
                a += __shfl_xor_sync(0xffffffffu, a, 1);
                a += __shfl_xor_sync(0xffffffffu, a, 2);
                d += __shfl_xor_sync(0xffffffffu, d, 1);
                d += __shfl_xor_sync(0xffffffffu, d, 2);
                sA[mt][rs][lh] = a; sD[mt][rs][lh] = d;
            }

    if (HH == 4) {
        if (lc == 0) {
#pragma unroll
            for (int mt = 0; mt < 2; mt++)
#pragma unroll
                for (int rs = 0; rs < 2; rs++) {
                    int row = rowbase + rg * 32 + mt * 16 + rs * 8 + lr;
                    if (row < M) {
#pragma unroll
                        for (int lh = 0; lh < LH; lh++) {
                            os[row * 4 + cg2 * 2 + lh] = sA[mt][rs][lh];
                            od[row * 4 + cg2 * 2 + lh] = sD[mt][rs][lh];
                        }
                    }
                }
        }
    } else {
        // single head spans both colgroup warps: combine via smem
        __syncthreads();
        float* sp = smem;            // 256 floats
        float* dp = smem + 256;      // 256 floats
        if (lc == 0) {
#pragma unroll
            for (int mt = 0; mt < 2; mt++)
#pragma unroll
                for (int rs = 0; rs < 2; rs++) {
                    int lrow = rg * 32 + mt * 16 + rs * 8 + lr;
                    sp[lrow * 2 + cg2] = sA[mt][rs][0];
                    dp[lrow * 2 + cg2] = sD[mt][rs][0];
                }
        }
        __syncthreads();
        if (tid < 128) {
            int row = rowbase + tid;
            if (row < M) {
                os[row] = sp[tid * 2] + sp[tid * 2 + 1];
                od[row] = dp[tid * 2] + dp[tid * 2 + 1];
            }
        }
    }
}

// ---------------------------------------------------------------------------
// CSR aggregation (unchanged).
// ---------------------------------------------------------------------------
__global__ __launch_bounds__(256) void agg128_k(const int* __restrict__ rowptr,
                                                const int* __restrict__ csrc,
                                                const float* __restrict__ feat,
                                                const float* __restrict__ as_,
                                                const float* __restrict__ ad_,
                                                const float* __restrict__ b,
                                                float* __restrict__ out, int N) {
    int gt = blockIdx.x * blockDim.x + threadIdx.x;
    int n = gt >> 5;
    int lane = gt & 31;
    if (n >= N) return;
    int h = lane >> 3;
    float adv = __ldg(ad_ + n * 4 + h);
    int p0 = __ldg(rowptr + n), p1 = __ldg(rowptr + n + 1);

    float den = 0.f;
    for (int i = p0; i < p1; i++) {
        int s = __ldg(csrc + i);
        float v = __ldg(as_ + s * 4 + h) + adv;
        v = v > 0.f ? v : 0.2f * v;
        den += __expf(v);
    }

    float4 acc = make_float4(0.f, 0.f, 0.f, 0.f);
    for (int i = p0; i < p1; i++) {
        int s = __ldg(csrc + i);
        float4 f = __ldg(reinterpret_cast<const float4*>(feat) + (size_t)s * 32 + lane);
        float v = __ldg(as_ + s * 4 + h) + adv;
        v = v > 0.f ? v : 0.2f * v;
        float ex = __expf(v);
        acc.x += ex * f.x; acc.y += ex * f.y;
        acc.z += ex * f.z; acc.w += ex * f.w;
    }

    float w = 1.f / (den + 1e-16f);
    float4 bb = *reinterpret_cast<const float4*>(b + lane * 4);
    float4 o;
    o.x = fmaxf(acc.x * w + bb.x, 0.f);
    o.y = fmaxf(acc.y * w + bb.y, 0.f);
    o.z = fmaxf(acc.z * w + bb.z, 0.f);
    o.w = fmaxf(acc.w * w + bb.w, 0.f);
    reinterpret_cast<float4*>(out)[(size_t)n * 32 + lane] = o;
}

__global__ __launch_bounds__(256) void agg64_k(const int* __restrict__ rowptr,
                                               const int* __restrict__ csrc,
                                               const float* __restrict__ feat,
                                               const float* __restrict__ as_,
                                               const float* __restrict__ ad_,
                                               const float* __restrict__ b,
                                               float* __restrict__ out, int N) {
    int gt = blockIdx.x * blockDim.x + threadIdx.x;
    int n = gt >> 5;
    int lane = gt & 31;
    if (n >= N) return;
    float adv = __ldg(ad_ + n);
    int p0 = __ldg(rowptr + n), p1 = __ldg(rowptr + n + 1);

    float den = 0.f;
    for (int i = p0; i < p1; i++) {
        int s = __ldg(csrc + i);
        float v = __ldg(as_ + s) + adv;
        v = v > 0.f ? v : 0.2f * v;
        den += __expf(v);
    }

    float2 acc = make_float2(0.f, 0.f);
    for (int i = p0; i < p1; i++) {
        int s = __ldg(csrc + i);
        float2 f = __ldg(reinterpret_cast<const float2*>(feat) + (size_t)s * 32 + lane);
        float v = __ldg(as_ + s) + adv;
        v = v > 0.f ? v : 0.2f * v;
        float ex = __expf(v);
        acc.x += ex * f.x; acc.y += ex * f.y;
    }

    float w = 1.f / (den + 1e-16f);
    float2 bb = *reinterpret_cast<const float2*>(b + lane * 2);
    float2 o;
    o.x = acc.x * w + bb.x;
    o.y = acc.y * w + bb.y;
    reinterpret_cast<float2*>(out)[(size_t)n * 32 + lane] = o;
}

// ---------------------------------------------------------------------------
extern "C" void kernel_launch(void* const* d_in, const int* in_sizes, int n_in,
                              void* d_out, int out_size) {
    const float* x   = (const float*)d_in[0];
    const void*  ei  = d_in[1];
    const float* W0  = (const float*)d_in[2];
    const float* as0 = (const float*)d_in[3];
    const float* ad0 = (const float*)d_in[4];
    const float* b0  = (const float*)d_in[5];
    const float* W1  = (const float*)d_in[6];
    const float* as1 = (const float*)d_in[7];
    const float* ad1 = (const float*)d_in[8];
    const float* b1  = (const float*)d_in[9];
    const float* W2  = (const float*)d_in[10];
    const float* as2 = (const float*)d_in[11];
    const float* ad2 = (const float*)d_in[12];
    const float* b2  = (const float*)d_in[13];
    float* out = (float*)d_out;

    int N = in_sizes[0] / 128;
    int E = in_sizes[1] / 2;
    int ET = E + N;

    float *feat, *inb, *asb, *adb;
    int *srcp, *dstp, *csrc, *cnt, *fill, *rowptr, *bsum;
    cudaGetSymbolAddress((void**)&feat,   g_feat);
    cudaGetSymbolAddress((void**)&inb,    g_in);
    cudaGetSymbolAddress((void**)&asb,    g_as);
    cudaGetSymbolAddress((void**)&adb,    g_ad);
    cudaGetSymbolAddress((void**)&srcp,   g_src);
    cudaGetSymbolAddress((void**)&dstp,   g_dst);
    cudaGetSymbolAddress((void**)&csrc,   g_csrc);
    cudaGetSymbolAddress((void**)&cnt,    g_cnt);
    cudaGetSymbolAddress((void**)&fill,   g_fill);
    cudaGetSymbolAddress((void**)&rowptr, g_rowptr);
    cudaGetSymbolAddress((void**)&bsum,   g_bsum);

    const int TB = 256;
    int gemmGrid = (N + 127) / 128;
    int aggGrid = ((long)N * 32 + TB - 1) / TB;
    int nchunk = (N + 1023) / 1024;

    const int SM128 = (128 * 68 + 64 * 132) * 4;   // 68608 B
    const int SM64  = (128 * 68 + 64 * 68) * 4;    // 52224 B
    cudaFuncSetAttribute(gemm_tc<128, 4>, cudaFuncAttributeMaxDynamicSharedMemorySize, SM128);
    cudaFuncSetAttribute(gemm_tc<64, 1>,  cudaFuncAttributeMaxDynamicSharedMemorySize, SM64);

    // ---- one-time CSR build ----
    detect_k<<<1, 1>>>((const unsigned int*)ei);
    zero_k<<<(N + TB - 1) / TB, TB>>>(cnt, fill, N);
    decode_hist_k<<<(ET + TB - 1) / TB, TB>>>(ei, E, ET, srcp, dstp, cnt);
    scan1_k<<<nchunk, 1024>>>(cnt, rowptr, bsum, N);
    scan2_k<<<1, 64>>>(bsum, nchunk, rowptr, N);
    scan3_k<<<(N + TB - 1) / TB, TB>>>(rowptr, bsum, N);
    scatter_k<<<(ET + TB - 1) / TB, TB>>>(srcp, dstp, ET, rowptr, fill, csrc);

    // ---------------- Layer 0 ----------------
    gemm_tc<128, 4><<<gemmGrid, TB, SM128>>>(x, W0, feat, as0, ad0, asb, adb, N);
    agg128_k<<<aggGrid, TB>>>(rowptr, csrc, feat, asb, adb, b0, inb, N);

    // ---------------- Layer 1 ----------------
    gemm_tc<128, 4><<<gemmGrid, TB, SM128>>>(inb, W1, feat, as1, ad1, asb, adb, N);
    agg128_k<<<aggGrid, TB>>>(rowptr, csrc, feat, asb, adb, b1, inb, N);

    // ---------------- Layer 2 ----------------
    gemm_tc<64, 1><<<gemmGrid, TB, SM64>>>(inb, W2, feat, as2, ad2, asb, adb, N);
    agg64_k<<<aggGrid, TB>>>(rowptr, csrc, feat, asb, adb, b2, out, N);
}

// round 10
// speedup vs baseline: 3.1734x; 1.1839x over previous
#include <cuda_runtime.h>
#include <cstdint>

// ---------------------------------------------------------------------------
// GAT encoder, 3 layers. Round 10: single-sweep aggregation (den and weighted
// sum accumulated together; normalize by division at the end). tf32 GEMM and
// CSR build unchanged from round 9 (260us).
// ---------------------------------------------------------------------------

#define MAXN 50000
#define MAXE 800000
#define MAXET (MAXE + MAXN)

__device__ __align__(16) float g_feat[MAXN * 128];
__device__ __align__(16) float g_in  [MAXN * 128];
__device__ __align__(16) float g_as  [MAXN * 4];
__device__ __align__(16) float g_ad  [MAXN * 4];
__device__ int g_src [MAXET];
__device__ int g_dst [MAXET];
__device__ int g_csrc[MAXET];
__device__ int g_cnt [MAXN];
__device__ int g_fill[MAXN];
__device__ int g_rowptr[MAXN + 1];
__device__ int g_bsum[64];
__device__ int g_is64;

// ---------------------------------------------------------------------------
__global__ void detect_k(const unsigned int* __restrict__ raw) {
    unsigned int o = 0;
#pragma unroll
    for (int j = 1; j < 128; j += 2) o |= raw[j];
    g_is64 = (o == 0u) ? 1 : 0;
}

__global__ void zero_k(int* __restrict__ cnt, int* __restrict__ fill, int N) {
    int i = blockIdx.x * blockDim.x + threadIdx.x;
    if (i < N) { cnt[i] = 0; fill[i] = 0; }
}

__global__ void decode_hist_k(const void* __restrict__ raw, int E, int ET,
                              int* __restrict__ src, int* __restrict__ dst,
                              int* __restrict__ cnt) {
    int e = blockIdx.x * blockDim.x + threadIdx.x;
    if (e >= ET) return;
    int s, d;
    if (e < E) {
        if (g_is64) {
            const long long* p = (const long long*)raw;
            s = (int)p[e];
            d = (int)p[E + e];
        } else {
            const int* p = (const int*)raw;
            s = p[e];
            d = p[E + e];
        }
    } else {
        s = d = e - E;
    }
    src[e] = s;
    dst[e] = d;
    atomicAdd(&cnt[d], 1);
}

__device__ __forceinline__ int warp_incl_scan(int v) {
    int lane = threadIdx.x & 31;
#pragma unroll
    for (int o = 1; o < 32; o <<= 1) {
        int t = __shfl_up_sync(0xffffffffu, v, o);
        if (lane >= o) v += t;
    }
    return v;
}

__global__ __launch_bounds__(1024) void scan1_k(const int* __restrict__ cnt,
                                                int* __restrict__ rowptr,
                                                int* __restrict__ bsum, int N) {
    __shared__ int wsum[32];
    int tid = threadIdx.x;
    int idx = blockIdx.x * 1024 + tid;
    int wid = tid >> 5, lane = tid & 31;
    int v = (idx < N) ? cnt[idx] : 0;
    int inc = warp_incl_scan(v);
    if (lane == 31) wsum[wid] = inc;
    __syncthreads();
    if (wid == 0) {
        int w = wsum[lane];
        wsum[lane] = warp_incl_scan(w);
    }
    __syncthreads();
    int off = (wid > 0) ? wsum[wid - 1] : 0;
    if (idx < N) rowptr[idx] = off + inc - v;
    if (tid == 1023) bsum[blockIdx.x] = off + inc;
}

__global__ void scan2_k(int* __restrict__ bsum, int nb, int* __restrict__ rowptr, int N) {
    __shared__ int sh[64];
    int tid = threadIdx.x;
    sh[tid] = (tid < nb) ? bsum[tid] : 0;
    __syncthreads();
    for (int o = 1; o < 64; o <<= 1) {
        int t = (tid >= o) ? sh[tid - o] : 0;
        __syncthreads();
        sh[tid] += t;
        __syncthreads();
    }
    if (tid < nb) bsum[tid] = (tid > 0) ? sh[tid - 1] : 0;
    if (tid == 0) rowptr[N] = sh[nb - 1];
}

__global__ void scan3_k(int* __restrict__ rowptr, const int* __restrict__ bsum, int N) {
    int idx = blockIdx.x * blockDim.x + threadIdx.x;
    if (idx < N) rowptr[idx] += bsum[idx >> 10];
}

__global__ void scatter_k(const int* __restrict__ src, const int* __restrict__ dst,
                          int ET, const int* __restrict__ rowptr,
                          int* __restrict__ fill, int* __restrict__ csrc) {
    int e = blockIdx.x * blockDim.x + threadIdx.x;
    if (e >= ET) return;
    int d = dst[e];
    int pos = rowptr[d] + atomicAdd(&fill[d], 1);
    csrc[pos] = src[e];
}

// ---------------------------------------------------------------------------
// tf32 helpers
// ---------------------------------------------------------------------------
__device__ __forceinline__ uint32_t f2tf(float f) {
    uint32_t u;
    asm("cvt.rna.tf32.f32 %0, %1;" : "=r"(u) : "f"(f));
    return u;
}

__device__ __forceinline__ void mma8(float4& d, const uint32_t* a, const uint32_t* b) {
    asm volatile(
        "mma.sync.aligned.m16n8k8.row.col.f32.tf32.tf32.f32 "
        "{%0,%1,%2,%3}, {%4,%5,%6,%7}, {%8,%9}, {%0,%1,%2,%3};"
        : "+f"(d.x), "+f"(d.y), "+f"(d.z), "+f"(d.w)
        : "r"(a[0]), "r"(a[1]), "r"(a[2]), "r"(a[3]), "r"(b[0]), "r"(b[1]));
}

// ---------------------------------------------------------------------------
// Tensor-core GEMM (unchanged from round 9).
// ---------------------------------------------------------------------------
template <int NC, int HH>
__global__ __launch_bounds__(256) void gemm_tc(const float* __restrict__ X,
                                               const float* __restrict__ W,
                                               float* __restrict__ O,
                                               const float* __restrict__ avs,
                                               const float* __restrict__ avd,
                                               float* __restrict__ os,
                                               float* __restrict__ od, int M) {
    constexpr int KC = 64;
    constexpr int XSS = 68;
    constexpr int WSS = NC + 4;
    constexpr int CGW = NC / 2;
    constexpr int NT  = CGW / 8;
    constexpr int LH  = (HH == 4) ? 2 : 1;

    extern __shared__ float smem[];
    float* Xs = smem;
    float* Ws = smem + 128 * XSS;

    int tid = threadIdx.x;
    int warp = tid >> 5, lane = tid & 31;
    int rg = warp >> 1, cg2 = warp & 1;
    int lr = lane >> 2, lc = lane & 3;
    int rowbase = blockIdx.x * 128;

    float4 acc[2][NT];
#pragma unroll
    for (int mt = 0; mt < 2; mt++)
#pragma unroll
        for (int nt = 0; nt < NT; nt++)
            acc[mt][nt] = make_float4(0.f, 0.f, 0.f, 0.f);

    for (int kb = 0; kb < 128; kb += KC) {
        __syncthreads();
#pragma unroll
        for (int i = 0; i < 8; i++) {
            int t = tid + i * 256;
            int row = t >> 4, q = t & 15;
            float4 v = make_float4(0.f, 0.f, 0.f, 0.f);
            if (rowbase + row < M)
                v = *reinterpret_cast<const float4*>(X + (size_t)(rowbase + row) * 128 + kb + q * 4);
            reinterpret_cast<float4*>(Xs + row * XSS)[q] = v;
        }
#pragma unroll
        for (int i = 0; i < (KC * NC / 4) / 256; i++) {
            int t = tid + i * 256;
            int k = t / (NC / 4), q = t % (NC / 4);
            float4 v = *reinterpret_cast<const float4*>(W + (size_t)(kb + k) * NC + q * 4);
            reinterpret_cast<float4*>(Ws + k * WSS)[q] = v;
        }
        __syncthreads();

#pragma unroll
        for (int kc = 0; kc < KC / 8; kc++) {
            uint32_t ah[2][4], al[2][4];
#pragma unroll
            for (int mt = 0; mt < 2; mt++) {
                const float* ab = Xs + (rg * 32 + mt * 16 + lr) * XSS + kc * 8 + lc;
                float f0 = ab[0];
                float f1 = ab[8 * XSS];
                float f2 = ab[4];
                float f3 = ab[8 * XSS + 4];
                ah[mt][0] = f2tf(f0); al[mt][0] = f2tf(f0 - __uint_as_float(ah[mt][0]));
                ah[mt][1] = f2tf(f1); al[mt][1] = f2tf(f1 - __uint_as_float(ah[mt][1]));
                ah[mt][2] = f2tf(f2); al[mt][2] = f2tf(f2 - __uint_as_float(ah[mt][2]));
                ah[mt][3] = f2tf(f3); al[mt][3] = f2tf(f3 - __uint_as_float(ah[mt][3]));
            }
#pragma unroll
            for (int nt = 0; nt < NT; nt++) {
                const float* bb = Ws + (kc * 8 + lc) * WSS + cg2 * CGW + nt * 8 + lr;
                float g0 = bb[0];
                float g1 = bb[4 * WSS];
                uint32_t bh[2], bl[2];
                bh[0] = f2tf(g0); bl[0] = f2tf(g0 - __uint_as_float(bh[0]));
                bh[1] = f2tf(g1); bl[1] = f2tf(g1 - __uint_as_float(bh[1]));
#pragma unroll
                for (int mt = 0; mt < 2; mt++) {
                    mma8(acc[mt][nt], ah[mt], bh);
                    mma8(acc[mt][nt], ah[mt], bl);
                    mma8(acc[mt][nt], al[mt], bh);
                }
            }
        }
    }

    float sA[2][2][LH], sD[2][2][LH];
#pragma unroll
    for (int mt = 0; mt < 2; mt++)
#pragma unroll
        for (int rs = 0; rs < 2; rs++)
#pragma unroll
            for (int lh = 0; lh < LH; lh++) { sA[mt][rs][lh] = 0.f; sD[mt][rs][lh] = 0.f; }

#pragma unroll
    for (int mt = 0; mt < 2; mt++) {
        int r0 = rowbase + rg * 32 + mt * 16 + lr;
#pragma unroll
        for (int nt = 0; nt < NT; nt++) {
            int col = cg2 * CGW + nt * 8 + 2 * lc;
            float4 d = acc[mt][nt];
            float av0 = __ldg(avs + col), av1 = __ldg(avs + col + 1);
            float dv0 = __ldg(avd + col), dv1 = __ldg(avd + col + 1);
            int lh = (HH == 4) ? (nt / (NT / 2)) : 0;
            sA[mt][0][lh] += d.x * av0 + d.y * av1;
            sD[mt][0][lh] += d.x * dv0 + d.y * dv1;
            sA[mt][1][lh] += d.z * av0 + d.w * av1;
            sD[mt][1][lh] += d.z * dv0 + d.w * dv1;
            if (r0 < M)
                *reinterpret_cast<float2*>(O + (size_t)r0 * NC + col) = make_float2(d.x, d.y);
            if (r0 + 8 < M)
                *reinterpret_cast<float2*>(O + (size_t)(r0 + 8) * NC + col) = make_float2(d.z, d.w);
        }
    }

#pragma unroll
    for (int mt = 0; mt < 2; mt++)
#pragma unroll
        for (int rs = 0; rs < 2; rs++)
#pragma unroll
            for (int lh = 0; lh < LH; lh++) {
                float a = sA[mt][rs][lh], d = sD[mt][rs][lh];
                a += __shfl_xor_sync(0xffffffffu, a, 1);
                a += __shfl_xor_sync(0xffffffffu, a, 2);
                d += __shfl_xor_sync(0xffffffffu, d, 1);
                d += __shfl_xor_sync(0xffffffffu, d, 2);
                sA[mt][rs][lh] = a; sD[mt][rs][lh] = d;
            }

    if (HH == 4) {
        if (lc == 0) {
#pragma unroll
            for (int mt = 0; mt < 2; mt++)
#pragma unroll
                for (int rs = 0; rs < 2; rs++) {
                    int row = rowbase + rg * 32 + mt * 16 + rs * 8 + lr;
                    if (row < M) {
#pragma unroll
                        for (int lh = 0; lh < LH; lh++) {
                            os[row * 4 + cg2 * 2 + lh] = sA[mt][rs][lh];
                            od[row * 4 + cg2 * 2 + lh] = sD[mt][rs][lh];
                        }
                    }
                }
        }
    } else {
        __syncthreads();
        float* sp = smem;
        float* dp = smem + 256;
        if (lc == 0) {
#pragma unroll
            for (int mt = 0; mt < 2; mt++)
#pragma unroll
                for (int rs = 0; rs < 2; rs++) {
                    int lrow = rg * 32 + mt * 16 + rs * 8 + lr;
                    sp[lrow * 2 + cg2] = sA[mt][rs][0];
                    dp[lrow * 2 + cg2] = sD[mt][rs][0];
                }
        }
        __syncthreads();
        if (tid < 128) {
            int row = rowbase + tid;
            if (row < M) {
                os[row] = sp[tid * 2] + sp[tid * 2 + 1];
                od[row] = dp[tid * 2] + dp[tid * 2 + 1];
            }
        }
    }
}

// ---------------------------------------------------------------------------
// CSR aggregation, single sweep: acc = sum ex*f, den = sum ex; out = acc/den.
// ---------------------------------------------------------------------------
__global__ __launch_bounds__(256) void agg128_k(const int* __restrict__ rowptr,
                                                const int* __restrict__ csrc,
                                                const float* __restrict__ feat,
                                                const float* __restrict__ as_,
                                                const float* __restrict__ ad_,
                                                const float* __restrict__ b,
                                                float* __restrict__ out, int N) {
    int gt = blockIdx.x * blockDim.x + threadIdx.x;
    int n = gt >> 5;
    int lane = gt & 31;
    if (n >= N) return;
    int h = lane >> 3;
    float adv = __ldg(ad_ + n * 4 + h);
    int p0 = __ldg(rowptr + n), p1 = __ldg(rowptr + n + 1);

    float den = 0.f;
    float4 acc = make_float4(0.f, 0.f, 0.f, 0.f);
    for (int i = p0; i < p1; i++) {
        int s = __ldg(csrc + i);
        float4 f = __ldg(reinterpret_cast<const float4*>(feat) + (size_t)s * 32 + lane);
        float v = __ldg(as_ + s * 4 + h) + adv;
        v = v > 0.f ? v : 0.2f * v;
        float ex = __expf(v);
        den += ex;
        acc.x += ex * f.x; acc.y += ex * f.y;
        acc.z += ex * f.z; acc.w += ex * f.w;
    }

    float w = 1.f / (den + 1e-16f);
    float4 bb = *reinterpret_cast<const float4*>(b + lane * 4);
    float4 o;
    o.x = fmaxf(acc.x * w + bb.x, 0.f);
    o.y = fmaxf(acc.y * w + bb.y, 0.f);
    o.z = fmaxf(acc.z * w + bb.z, 0.f);
    o.w = fmaxf(acc.w * w + bb.w, 0.f);
    reinterpret_cast<float4*>(out)[(size_t)n * 32 + lane] = o;
}

__global__ __launch_bounds__(256) void agg64_k(const int* __restrict__ rowptr,
                                               const int* __restrict__ csrc,
                                               const float* __restrict__ feat,
                                               const float* __restrict__ as_,
                                               const float* __restrict__ ad_,
                                               const float* __restrict__ b,
                                               float* __restrict__ out, int N) {
    int gt = blockIdx.x * blockDim.x + threadIdx.x;
    int n = gt >> 5;
    int lane = gt & 31;
    if (n >= N) return;
    float adv = __ldg(ad_ + n);
    int p0 = __ldg(rowptr + n), p1 = __ldg(rowptr + n + 1);

    float den = 0.f;
    float2 acc = make_float2(0.f, 0.f);
    for (int i = p0; i < p1; i++) {
        int s = __ldg(csrc + i);
        float2 f = __ldg(reinterpret_cast<const float2*>(feat) + (size_t)s * 32 + lane);
        float v = __ldg(as_ + s) + adv;
        v = v > 0.f ? v : 0.2f * v;
        float ex = __expf(v);
        den += ex;
        acc.x += ex * f.x; acc.y += ex * f.y;
    }

    float w = 1.f / (den + 1e-16f);
    float2 bb = *reinterpret_cast<const float2*>(b + lane * 2);
    float2 o;
    o.x = acc.x * w + bb.x;
    o.y = acc.y * w + bb.y;
    reinterpret_cast<float2*>(out)[(size_t)n * 32 + lane] = o;
}

// ---------------------------------------------------------------------------
extern "C" void kernel_launch(void* const* d_in, const int* in_sizes, int n_in,
                              void* d_out, int out_size) {
    const float* x   = (const float*)d_in[0];
    const void*  ei  = d_in[1];
    const float* W0  = (const float*)d_in[2];
    const float* as0 = (const float*)d_in[3];
    const float* ad0 = (const float*)d_in[4];
    const float* b0  = (const float*)d_in[5];
    const float* W1  = (const float*)d_in[6];
    const float* as1 = (const float*)d_in[7];
    const float* ad1 = (const float*)d_in[8];
    const float* b1  = (const float*)d_in[9];
    const float* W2  = (const float*)d_in[10];
    const float* as2 = (const float*)d_in[11];
    const float* ad2 = (const float*)d_in[12];
    const float* b2  = (const float*)d_in[13];
    float* out = (float*)d_out;

    int N = in_sizes[0] / 128;
    int E = in_sizes[1] / 2;
    int ET = E + N;

    float *feat, *inb, *asb, *adb;
    int *srcp, *dstp, *csrc, *cnt, *fill, *rowptr, *bsum;
    cudaGetSymbolAddress((void**)&feat,   g_feat);
    cudaGetSymbolAddress((void**)&inb,    g_in);
    cudaGetSymbolAddress((void**)&asb,    g_as);
    cudaGetSymbolAddress((void**)&adb,    g_ad);
    cudaGetSymbolAddress((void**)&srcp,   g_src);
    cudaGetSymbolAddress((void**)&dstp,   g_dst);
    cudaGetSymbolAddress((void**)&csrc,   g_csrc);
    cudaGetSymbolAddress((void**)&cnt,    g_cnt);
    cudaGetSymbolAddress((void**)&fill,   g_fill);
    cudaGetSymbolAddress((void**)&rowptr, g_rowptr);
    cudaGetSymbolAddress((void**)&bsum,   g_bsum);

    const int TB = 256;
    int gemmGrid = (N + 127) / 128;
    int aggGrid = ((long)N * 32 + TB - 1) / TB;
    int nchunk = (N + 1023) / 1024;

    const int SM128 = (128 * 68 + 64 * 132) * 4;   // 68608 B
    const int SM64  = (128 * 68 + 64 * 68) * 4;    // 52224 B
    cudaFuncSetAttribute(gemm_tc<128, 4>, cudaFuncAttributeMaxDynamicSharedMemorySize, SM128);
    cudaFuncSetAttribute(gemm_tc<64, 1>,  cudaFuncAttributeMaxDynamicSharedMemorySize, SM64);

    // ---- one-time CSR build ----
    detect_k<<<1, 1>>>((const unsigned int*)ei);
    zero_k<<<(N + TB - 1) / TB, TB>>>(cnt, fill, N);
    decode_hist_k<<<(ET + TB - 1) / TB, TB>>>(ei, E, ET, srcp, dstp, cnt);
    scan1_k<<<nchunk, 1024>>>(cnt, rowptr, bsum, N);
    scan2_k<<<1, 64>>>(bsum, nchunk, rowptr, N);
    scan3_k<<<(N + TB - 1) / TB, TB>>>(rowptr, bsum, N);
    scatter_k<<<(ET + TB - 1) / TB, TB>>>(srcp, dstp, ET, rowptr, fill, csrc);

    // ---------------- Layer 0 ----------------
    gemm_tc<128, 4><<<gemmGrid, TB, SM128>>>(x, W0, feat, as0, ad0, asb, adb, N);
    agg128_k<<<aggGrid, TB>>>(rowptr, csrc, feat, asb, adb, b0, inb, N);

    // ---------------- Layer 1 ----------------
    gemm_tc<128, 4><<<gemmGrid, TB, SM128>>>(inb, W1, feat, as1, ad1, asb, adb, N);
    agg128_k<<<aggGrid, TB>>>(rowptr, csrc, feat, asb, adb, b1, inb, N);

    // ---------------- Layer 2 ----------------
    gemm_tc<64, 1><<<gemmGrid, TB, SM64>>>(inb, W2, feat, as2, ad2, asb, adb, N);
    agg64_k<<<aggGrid, TB>>>(rowptr, csrc, feat, asb, adb, b2, out, N);
}